// round 1
// baseline (speedup 1.0000x reference)
#include <cuda_runtime.h>
#include <math.h>

#define B_SZ 2
#define T_SZ 2048
#define C_SZ 2048
#define NH   16
#define NKV  4
#define HD   128

// Scratch (allocation-free rule: __device__ globals)
__device__ float g_q[B_SZ * T_SZ * NH  * HD];   // [B*T, 2048]
__device__ float g_k[B_SZ * T_SZ * NKV * HD];   // [B*T, 512]
__device__ float g_v[B_SZ * T_SZ * NKV * HD];   // [B*T, 512]
__device__ float g_y[B_SZ * T_SZ * NH  * HD];   // [B*T, 2048]

// ---------------------------------------------------------------------------
// Generic fp32 GEMM: C[M,N] = A[M,K] @ B[K,N], all row-major.
// 64x64x16 tiles, 256 threads, 4x4 per-thread microtile.
// M % 64 == 0, N % 64 == 0, K % 16 == 0 (holds for all our shapes).
// ---------------------------------------------------------------------------
__global__ void gemm64(const float* __restrict__ A, const float* __restrict__ Bm,
                       float* __restrict__ C, int M, int N, int K) {
    __shared__ float As[16][64];   // [k][m]
    __shared__ float Bs[16][64];   // [k][n]

    const int tid = threadIdx.x;
    const int bm = blockIdx.y * 64;
    const int bn = blockIdx.x * 64;
    const int tx = tid & 15;       // 0..15 -> n microtile
    const int ty = tid >> 4;       // 0..15 -> m microtile

    // A load mapping: 64 rows x 16 k; float4 along k
    const int am = tid >> 2;            // 0..63
    const int ak = (tid & 3) * 4;       // 0,4,8,12
    // B load mapping: 16 k x 64 n; float4 along n
    const int bk  = tid >> 4;           // 0..15
    const int bn4 = (tid & 15) * 4;     // 0..60

    const float* Ap = A + (size_t)(bm + am) * K + ak;
    const float* Bp = Bm + (size_t)bk * N + bn + bn4;

    float acc[4][4];
#pragma unroll
    for (int i = 0; i < 4; i++)
#pragma unroll
        for (int j = 0; j < 4; j++) acc[i][j] = 0.f;

    for (int k0 = 0; k0 < K; k0 += 16) {
        float4 a4 = *(const float4*)Ap;
        float4 b4 = *(const float4*)Bp;
        Ap += 16;
        Bp += (size_t)16 * N;

        As[ak + 0][am] = a4.x;
        As[ak + 1][am] = a4.y;
        As[ak + 2][am] = a4.z;
        As[ak + 3][am] = a4.w;
        *(float4*)&Bs[bk][bn4] = b4;
        __syncthreads();

#pragma unroll
        for (int kk = 0; kk < 16; kk++) {
            float4 av = *(const float4*)&As[kk][ty * 4];
            float4 bv = *(const float4*)&Bs[kk][tx * 4];
            float ar[4] = {av.x, av.y, av.z, av.w};
            float br[4] = {bv.x, bv.y, bv.z, bv.w};
#pragma unroll
            for (int i = 0; i < 4; i++)
#pragma unroll
                for (int j = 0; j < 4; j++)
                    acc[i][j] = fmaf(ar[i], br[j], acc[i][j]);
        }
        __syncthreads();
    }

    float* Cp = C + (size_t)(bm + ty * 4) * N + bn + tx * 4;
#pragma unroll
    for (int i = 0; i < 4; i++) {
        float4 r = make_float4(acc[i][0], acc[i][1], acc[i][2], acc[i][3]);
        *(float4*)(Cp + (size_t)i * N) = r;
    }
}

// ---------------------------------------------------------------------------
// In-place RoPE on [B*T, nheads*128]; one thread per (row, head, pair).
// out[d]    = x[d]*cos - x[d+64]*sin        (d < 64)
// out[d+64] = x[d+64]*cos + x[d]*sin
// ---------------------------------------------------------------------------
__global__ void rope_inplace(float* __restrict__ X, int nheads) {
    int idx = blockIdx.x * blockDim.x + threadIdx.x;
    int total = B_SZ * T_SZ * nheads * 64;
    if (idx >= total) return;
    int dp   = idx & 63;
    int rest = idx >> 6;
    int h    = rest % nheads;
    int bt   = rest / nheads;
    int t    = bt & (T_SZ - 1);

    float inv_freq = powf(10000.0f, -(float)(2 * dp) * (1.0f / 128.0f));
    float ang = (float)t * inv_freq;
    float sv, cv;
    sincosf(ang, &sv, &cv);

    float* p = X + (size_t)bt * (nheads * HD) + h * HD + dp;
    float x0 = p[0], x1 = p[64];
    p[0]  = x0 * cv - x1 * sv;
    p[64] = x1 * cv + x0 * sv;
}

// ---------------------------------------------------------------------------
// Flash attention, fp32, causal, GQA (kv head = h/4).
// Grid: (T/64, B*H). 256 threads = 8 warps, warp w owns query rows w*8..w*8+7.
// Smem: Qs[64][128], Kt[128][65] (transposed, padded), Vs[64][128], Ps[64][64]
// ---------------------------------------------------------------------------
__global__ void flash_attn(const float* __restrict__ Q, const float* __restrict__ K,
                           const float* __restrict__ V, float* __restrict__ Y) {
    extern __shared__ float sm[];
    float* Qs = sm;                 // 8192 floats
    float* Kt = sm + 8192;          // 128*65 = 8320
    float* Vs = sm + 16512;         // 8192
    float* Ps = sm + 24704;         // 4096   (total 28800 floats = 115200 B)

    const int bi  = blockIdx.x;             // query tile
    const int bh  = blockIdx.y;             // b*16 + h
    const int b   = bh >> 4, h = bh & 15;
    const int kvh = h >> 2;
    const int tid = threadIdx.x;
    const int warp = tid >> 5, lane = tid & 31;
    const float scale = 0.08838834764831845f;  // 1/sqrt(128)

    // Load + scale Q tile: rows t = bi*64 + r
    {
        const float* qb = Q + (size_t)(b * T_SZ + bi * 64) * (NH * HD) + h * HD;
#pragma unroll
        for (int it = 0; it < 8; it++) {
            int r  = warp + 8 * it;
            int d4 = lane * 4;
            float4 v4 = *(const float4*)(qb + (size_t)r * (NH * HD) + d4);
            Qs[r * 128 + d4 + 0] = v4.x * scale;
            Qs[r * 128 + d4 + 1] = v4.y * scale;
            Qs[r * 128 + d4 + 2] = v4.z * scale;
            Qs[r * 128 + d4 + 3] = v4.w * scale;
        }
    }

    float o[8][4];
    float mrow[8], lrow[8];
#pragma unroll
    for (int r8 = 0; r8 < 8; r8++) {
        mrow[r8] = -1e30f;
        lrow[r8] = 0.f;
        o[r8][0] = o[r8][1] = o[r8][2] = o[r8][3] = 0.f;
    }

    for (int j = 0; j <= bi; j++) {
        __syncthreads();  // previous tile's smem fully consumed (and Qs ready, 1st iter)
        const float* kb = K + (size_t)(b * T_SZ + j * 64) * (NKV * HD) + kvh * HD;
        const float* vb = V + (size_t)(b * T_SZ + j * 64) * (NKV * HD) + kvh * HD;
#pragma unroll
        for (int it = 0; it < 8; it++) {
            int c  = warp + 8 * it;
            int d4 = lane * 4;
            float4 k4 = *(const float4*)(kb + (size_t)c * (NKV * HD) + d4);
            Kt[(d4 + 0) * 65 + c] = k4.x;
            Kt[(d4 + 1) * 65 + c] = k4.y;
            Kt[(d4 + 2) * 65 + c] = k4.z;
            Kt[(d4 + 3) * 65 + c] = k4.w;
            float4 v4 = *(const float4*)(vb + (size_t)c * (NKV * HD) + d4);
            *(float4*)&Vs[c * 128 + d4] = v4;
        }
        __syncthreads();

        // S = Q K^T : lane owns cols (lane, lane+32) for 8 rows
        float s[8][2];
#pragma unroll
        for (int r8 = 0; r8 < 8; r8++) { s[r8][0] = 0.f; s[r8][1] = 0.f; }
#pragma unroll 4
        for (int d = 0; d < 128; d++) {
            float k0 = Kt[d * 65 + lane];
            float k1 = Kt[d * 65 + lane + 32];
#pragma unroll
            for (int r8 = 0; r8 < 8; r8++) {
                float qv = Qs[(warp * 8 + r8) * 128 + d];
                s[r8][0] = fmaf(qv, k0, s[r8][0]);
                s[r8][1] = fmaf(qv, k1, s[r8][1]);
            }
        }

        const bool diag = (j == bi);
#pragma unroll
        for (int r8 = 0; r8 < 8; r8++) {
            int r = warp * 8 + r8;
            float s0 = s[r8][0], s1 = s[r8][1];
            if (diag) {
                if (lane > r)      s0 = -1e30f;
                if (lane + 32 > r) s1 = -1e30f;
            }
            float mx = fmaxf(s0, s1);
#pragma unroll
            for (int off = 16; off; off >>= 1)
                mx = fmaxf(mx, __shfl_xor_sync(0xffffffffu, mx, off));
            float mnew  = fmaxf(mrow[r8], mx);
            float alpha = __expf(mrow[r8] - mnew);
            float p0 = __expf(s0 - mnew);
            float p1 = __expf(s1 - mnew);
            float ls = p0 + p1;
#pragma unroll
            for (int off = 16; off; off >>= 1)
                ls += __shfl_xor_sync(0xffffffffu, ls, off);
            lrow[r8] = lrow[r8] * alpha + ls;
            mrow[r8] = mnew;
            o[r8][0] *= alpha; o[r8][1] *= alpha;
            o[r8][2] *= alpha; o[r8][3] *= alpha;
            Ps[r * 64 + lane]      = p0;
            Ps[r * 64 + lane + 32] = p1;
        }
        __syncwarp();  // Ps written by all lanes of this warp, read cross-lane below

        // O += P V : lane owns d = lane + 32*jj
#pragma unroll 2
        for (int c = 0; c < 64; c++) {
            float v0 = Vs[c * 128 + lane];
            float v1 = Vs[c * 128 + lane + 32];
            float v2 = Vs[c * 128 + lane + 64];
            float v3 = Vs[c * 128 + lane + 96];
#pragma unroll
            for (int r8 = 0; r8 < 8; r8++) {
                float p = Ps[(warp * 8 + r8) * 64 + c];
                o[r8][0] = fmaf(p, v0, o[r8][0]);
                o[r8][1] = fmaf(p, v1, o[r8][1]);
                o[r8][2] = fmaf(p, v2, o[r8][2]);
                o[r8][3] = fmaf(p, v3, o[r8][3]);
            }
        }
    }

    // Write normalized output: y[b, t, h*128 + d]
#pragma unroll
    for (int r8 = 0; r8 < 8; r8++) {
        int r = warp * 8 + r8;
        float inv = 1.f / lrow[r8];
        float* yb = Y + (size_t)(b * T_SZ + bi * 64 + r) * (NH * HD) + h * HD;
        yb[lane]      = o[r8][0] * inv;
        yb[lane + 32] = o[r8][1] * inv;
        yb[lane + 64] = o[r8][2] * inv;
        yb[lane + 96] = o[r8][3] * inv;
    }
}

// ---------------------------------------------------------------------------
extern "C" void kernel_launch(void* const* d_in, const int* in_sizes, int n_in,
                              void* d_out, int out_size) {
    const float* x  = (const float*)d_in[0];
    const float* wq = (const float*)d_in[1];
    const float* wk = (const float*)d_in[2];
    const float* wv = (const float*)d_in[3];
    const float* wo = (const float*)d_in[4];
    float* out = (float*)d_out;

    float *qp, *kp, *vp, *yp;
    cudaGetSymbolAddress((void**)&qp, g_q);
    cudaGetSymbolAddress((void**)&kp, g_k);
    cudaGetSymbolAddress((void**)&vp, g_v);
    cudaGetSymbolAddress((void**)&yp, g_y);

    const int M = B_SZ * T_SZ;  // 4096

    // QKV projections
    gemm64<<<dim3(2048 / 64, M / 64), 256>>>(x, wq, qp, M, 2048, 2048);
    gemm64<<<dim3(512 / 64,  M / 64), 256>>>(x, wk, kp, M, 512, 2048);
    gemm64<<<dim3(512 / 64,  M / 64), 256>>>(x, wv, vp, M, 512, 2048);

    // RoPE in place on q and k
    {
        int totq = M * NH * 64;
        rope_inplace<<<(totq + 255) / 256, 256>>>(qp, NH);
        int totk = M * NKV * 64;
        rope_inplace<<<(totk + 255) / 256, 256>>>(kp, NKV);
    }

    // Causal GQA flash attention
    cudaFuncSetAttribute(flash_attn, cudaFuncAttributeMaxDynamicSharedMemorySize, 115200);
    flash_attn<<<dim3(T_SZ / 64, B_SZ * NH), 256, 115200>>>(qp, kp, vp, yp);

    // Output projection
    gemm64<<<dim3(2048 / 64, M / 64), 256>>>(yp, wo, out, M, 2048, 2048);
}

// round 3
// speedup vs baseline: 1.8708x; 1.8708x over previous
#include <cuda_runtime.h>
#include <math.h>
#include <cstdint>

#define B_SZ 2
#define T_SZ 2048
#define NH   16
#define NKV  4
#define HD   128
#define MR   (B_SZ * T_SZ)   // 4096 rows
#define KC   2048            // inner dim of all GEMMs

// ---------------- scratch (__device__ globals: allocation-free rule) --------
__device__ float g_q  [MR * NH  * HD];
__device__ float g_k  [MR * NKV * HD];
__device__ float g_v  [MR * NKV * HD];
__device__ float g_y  [MR * NH  * HD];
__device__ float g_xr [MR * 2048];       // x rounded to tf32
__device__ float g_wqT[2048 * 2048];     // W^T, tf32-rounded (row-major [N,K])
__device__ float g_wkT[512  * 2048];
__device__ float g_wvT[512  * 2048];
__device__ float g_woT[2048 * 2048];

// ---------------- PTX helpers (all baseline compute_103-safe) ---------------
__device__ __forceinline__ float rna_tf32(float x) {
    uint32_t u;
    asm("cvt.rna.tf32.f32 %0, %1;" : "=r"(u) : "f"(x));
    return __uint_as_float(u);
}
__device__ __forceinline__ void cp16(uint32_t s, const void* g) {
    asm volatile("cp.async.cg.shared.global [%0], [%1], 16;" :: "r"(s), "l"(g));
}
__device__ __forceinline__ void cp_commit() {
    asm volatile("cp.async.commit_group;" ::: "memory");
}
template <int N> __device__ __forceinline__ void cp_wait() {
    asm volatile("cp.async.wait_group %0;" :: "n"(N) : "memory");
}
__device__ __forceinline__ void mma_tf32(float* c, const uint32_t* a, const uint32_t* b) {
    asm volatile(
        "mma.sync.aligned.m16n8k8.row.col.f32.tf32.tf32.f32 "
        "{%0,%1,%2,%3}, {%4,%5,%6,%7}, {%8,%9}, {%0,%1,%2,%3};"
        : "+f"(c[0]), "+f"(c[1]), "+f"(c[2]), "+f"(c[3])
        : "r"(a[0]), "r"(a[1]), "r"(a[2]), "r"(a[3]), "r"(b[0]), "r"(b[1]));
}

// ---------------------------------------------------------------------------
// tf32 mma.sync GEMM: C[M, N] = A[M, 2048] @ BT[N, 2048]^T  (A, BT row-major)
// 128x128x32 CTA tile, 256 threads (8 warps = 2m x 4n), warp tile 64x32.
// 3-stage cp.async pipeline; smem rows padded to 36 floats (conflict-free).
// ---------------------------------------------------------------------------
#define BM 128
#define BN 128
#define BK 32
#define PAD 36
#define STG_FLOATS (2 * 128 * PAD)                 // A + B per stage
#define GEMM_SMEM  (3 * STG_FLOATS * 4)            // 110592 B

__device__ __forceinline__ void g_fill(float* smf, uint32_t smb, int st, int ck, int tid,
                                       const float* Ab, const float* Bb) {
    uint32_t sa = smb + st * (STG_FLOATS * 4);
    uint32_t sb = sa + 128 * PAD * 4;
    const float* Ac = Ab + ck * BK;
    const float* Bc = Bb + ck * BK;
#pragma unroll
    for (int u = 0; u < 4; u++) {
        int idx = u * 256 + tid;
        int r = idx >> 3, c4 = (idx & 7) * 4;
        cp16(sa + (r * PAD + c4) * 4, Ac + (size_t)r * KC + c4);
    }
#pragma unroll
    for (int u = 0; u < 4; u++) {
        int idx = u * 256 + tid;
        int r = idx >> 3, c4 = (idx & 7) * 4;
        cp16(sb + (r * PAD + c4) * 4, Bc + (size_t)r * KC + c4);
    }
    cp_commit();
}

__global__ void __launch_bounds__(256, 1)
gemm_mma(const float* __restrict__ A, const float* __restrict__ BT,
         float* __restrict__ C, int N) {
    extern __shared__ float smf[];
    uint32_t smb = (uint32_t)__cvta_generic_to_shared(smf);

    const int tid  = threadIdx.x;
    const int lane = tid & 31;
    const int warp = tid >> 5;
    const int wm   = (warp >> 2) * 64;   // 0 or 64
    const int wn   = (warp & 3) * 32;    // 0,32,64,96
    const int bm   = blockIdx.y * BM;
    const int bn   = blockIdx.x * BN;

    const float* Ab = A  + (size_t)bm * KC;
    const float* Bb = BT + (size_t)bn * KC;

    float acc[4][4][4];
#pragma unroll
    for (int i = 0; i < 4; i++)
#pragma unroll
        for (int j = 0; j < 4; j++)
#pragma unroll
            for (int r = 0; r < 4; r++) acc[i][j][r] = 0.f;

    g_fill(smf, smb, 0, 0, tid, Ab, Bb);
    g_fill(smf, smb, 1, 1, tid, Ab, Bb);

    const int lr = lane >> 2;   // 0..7
    const int lc = lane & 3;    // 0..3
    const int NCK = KC / BK;    // 64

    for (int i = 0; i < NCK; i++) {
        cp_wait<1>();
        __syncthreads();
        if (i + 2 < NCK) g_fill(smf, smb, (i + 2) % 3, i + 2, tid, Ab, Bb);

        const float* As = smf + (i % 3) * STG_FLOATS;
        const float* Bs = As + 128 * PAD;

#pragma unroll
        for (int ks = 0; ks < 4; ks++) {
            uint32_t a[4][4], b[4][2];
#pragma unroll
            for (int mf = 0; mf < 4; mf++) {
                const float* p = As + (wm + mf * 16 + lr) * PAD + ks * 8 + lc;
                a[mf][0] = __float_as_uint(p[0]);
                a[mf][1] = __float_as_uint(p[8 * PAD]);
                a[mf][2] = __float_as_uint(p[4]);
                a[mf][3] = __float_as_uint(p[8 * PAD + 4]);
            }
#pragma unroll
            for (int nf = 0; nf < 4; nf++) {
                const float* q = Bs + (wn + nf * 8 + lr) * PAD + ks * 8 + lc;
                b[nf][0] = __float_as_uint(q[0]);
                b[nf][1] = __float_as_uint(q[4]);
            }
#pragma unroll
            for (int mf = 0; mf < 4; mf++)
#pragma unroll
                for (int nf = 0; nf < 4; nf++)
                    mma_tf32(acc[mf][nf], a[mf], b[nf]);
        }
        __syncthreads();
    }

    // epilogue: c0,c1 -> (row, 2*lc), (row, 2*lc+1); c2,c3 -> row+8
#pragma unroll
    for (int mf = 0; mf < 4; mf++) {
        int row0 = bm + wm + mf * 16 + lr;
#pragma unroll
        for (int nf = 0; nf < 4; nf++) {
            int col = bn + wn + nf * 8 + lc * 2;
            float2 v0 = make_float2(acc[mf][nf][0], acc[mf][nf][1]);
            float2 v1 = make_float2(acc[mf][nf][2], acc[mf][nf][3]);
            *(float2*)(C + (size_t)row0 * N + col)       = v0;
            *(float2*)(C + (size_t)(row0 + 8) * N + col) = v1;
        }
    }
}

// ---------------------------------------------------------------------------
// Weight transpose + tf32-round: WT[n][k] = rna(W[k][n]); W is [K, N]
// ---------------------------------------------------------------------------
__global__ void transpose_rna(const float* __restrict__ W, float* __restrict__ WT,
                              int K, int N) {
    __shared__ float t[32][33];
    int n0 = blockIdx.x * 32, k0 = blockIdx.y * 32;
    int tx = threadIdx.x, ty = threadIdx.y;  // (32, 8)
#pragma unroll
    for (int i = 0; i < 4; i++)
        t[ty + 8 * i][tx] = W[(size_t)(k0 + ty + 8 * i) * N + n0 + tx];
    __syncthreads();
#pragma unroll
    for (int i = 0; i < 4; i++)
        WT[(size_t)(n0 + ty + 8 * i) * K + k0 + tx] = rna_tf32(t[tx][ty + 8 * i]);
}

__global__ void round_x(const float* __restrict__ X, float* __restrict__ XR, int n4) {
    int i = blockIdx.x * blockDim.x + threadIdx.x;
    if (i >= n4) return;
    float4 v = ((const float4*)X)[i];
    v.x = rna_tf32(v.x); v.y = rna_tf32(v.y);
    v.z = rna_tf32(v.z); v.w = rna_tf32(v.w);
    ((float4*)XR)[i] = v;
}

// ---------------------------------------------------------------------------
// In-place RoPE on [B*T, nheads*128]
// ---------------------------------------------------------------------------
__global__ void rope_inplace(float* __restrict__ X, int nheads) {
    int idx = blockIdx.x * blockDim.x + threadIdx.x;
    int total = MR * 64 * nheads;
    if (idx >= total) return;
    int dp   = idx & 63;
    int rest = idx >> 6;
    int h    = rest % nheads;
    int bt   = rest / nheads;
    int t    = bt & (T_SZ - 1);

    float inv_freq = powf(10000.0f, -(float)(2 * dp) * (1.0f / 128.0f));
    float ang = (float)t * inv_freq;
    float sv, cv;
    sincosf(ang, &sv, &cv);

    float* p = X + (size_t)bt * (nheads * HD) + h * HD + dp;
    float x0 = p[0], x1 = p[64];
    p[0]  = x0 * cv - x1 * sv;
    p[64] = x1 * cv + x0 * sv;
}

// ---------------------------------------------------------------------------
// Flash attention, fp32, causal, GQA (kv head = h/4). Output tf32-rounded
// so the final mma GEMM sees exact tf32 operands.
// ---------------------------------------------------------------------------
__global__ void flash_attn(const float* __restrict__ Q, const float* __restrict__ K,
                           const float* __restrict__ V, float* __restrict__ Y) {
    extern __shared__ float sm[];
    float* Qs = sm;
    float* Kt = sm + 8192;
    float* Vs = sm + 16512;
    float* Ps = sm + 24704;

    const int bi  = blockIdx.x;
    const int bh  = blockIdx.y;
    const int b   = bh >> 4, h = bh & 15;
    const int kvh = h >> 2;
    const int tid = threadIdx.x;
    const int warp = tid >> 5, lane = tid & 31;
    const float scale = 0.08838834764831845f;

    {
        const float* qb = Q + (size_t)(b * T_SZ + bi * 64) * (NH * HD) + h * HD;
#pragma unroll
        for (int it = 0; it < 8; it++) {
            int r  = warp + 8 * it;
            int d4 = lane * 4;
            float4 v4 = *(const float4*)(qb + (size_t)r * (NH * HD) + d4);
            Qs[r * 128 + d4 + 0] = v4.x * scale;
            Qs[r * 128 + d4 + 1] = v4.y * scale;
            Qs[r * 128 + d4 + 2] = v4.z * scale;
            Qs[r * 128 + d4 + 3] = v4.w * scale;
        }
    }

    float o[8][4];
    float mrow[8], lrow[8];
#pragma unroll
    for (int r8 = 0; r8 < 8; r8++) {
        mrow[r8] = -1e30f; lrow[r8] = 0.f;
        o[r8][0] = o[r8][1] = o[r8][2] = o[r8][3] = 0.f;
    }

    for (int j = 0; j <= bi; j++) {
        __syncthreads();
        const float* kb = K + (size_t)(b * T_SZ + j * 64) * (NKV * HD) + kvh * HD;
        const float* vb = V + (size_t)(b * T_SZ + j * 64) * (NKV * HD) + kvh * HD;
#pragma unroll
        for (int it = 0; it < 8; it++) {
            int c  = warp + 8 * it;
            int d4 = lane * 4;
            float4 k4 = *(const float4*)(kb + (size_t)c * (NKV * HD) + d4);
            Kt[(d4 + 0) * 65 + c] = k4.x;
            Kt[(d4 + 1) * 65 + c] = k4.y;
            Kt[(d4 + 2) * 65 + c] = k4.z;
            Kt[(d4 + 3) * 65 + c] = k4.w;
            float4 v4 = *(const float4*)(vb + (size_t)c * (NKV * HD) + d4);
            *(float4*)&Vs[c * 128 + d4] = v4;
        }
        __syncthreads();

        float s[8][2];
#pragma unroll
        for (int r8 = 0; r8 < 8; r8++) { s[r8][0] = 0.f; s[r8][1] = 0.f; }
#pragma unroll 4
        for (int d = 0; d < 128; d++) {
            float k0 = Kt[d * 65 + lane];
            float k1 = Kt[d * 65 + lane + 32];
#pragma unroll
            for (int r8 = 0; r8 < 8; r8++) {
                float qv = Qs[(warp * 8 + r8) * 128 + d];
                s[r8][0] = fmaf(qv, k0, s[r8][0]);
                s[r8][1] = fmaf(qv, k1, s[r8][1]);
            }
        }

        const bool diag = (j == bi);
#pragma unroll
        for (int r8 = 0; r8 < 8; r8++) {
            int r = warp * 8 + r8;
            float s0 = s[r8][0], s1 = s[r8][1];
            if (diag) {
                if (lane > r)      s0 = -1e30f;
                if (lane + 32 > r) s1 = -1e30f;
            }
            float mx = fmaxf(s0, s1);
#pragma unroll
            for (int off = 16; off; off >>= 1)
                mx = fmaxf(mx, __shfl_xor_sync(0xffffffffu, mx, off));
            float mnew  = fmaxf(mrow[r8], mx);
            float alpha = __expf(mrow[r8] - mnew);
            float p0 = __expf(s0 - mnew);
            float p1 = __expf(s1 - mnew);
            float ls = p0 + p1;
#pragma unroll
            for (int off = 16; off; off >>= 1)
                ls += __shfl_xor_sync(0xffffffffu, ls, off);
            lrow[r8] = lrow[r8] * alpha + ls;
            mrow[r8] = mnew;
            o[r8][0] *= alpha; o[r8][1] *= alpha;
            o[r8][2] *= alpha; o[r8][3] *= alpha;
            Ps[r * 64 + lane]      = p0;
            Ps[r * 64 + lane + 32] = p1;
        }
        __syncwarp();

#pragma unroll 2
        for (int c = 0; c < 64; c++) {
            float v0 = Vs[c * 128 + lane];
            float v1 = Vs[c * 128 + lane + 32];
            float v2 = Vs[c * 128 + lane + 64];
            float v3 = Vs[c * 128 + lane + 96];
#pragma unroll
            for (int r8 = 0; r8 < 8; r8++) {
                float p = Ps[(warp * 8 + r8) * 64 + c];
                o[r8][0] = fmaf(p, v0, o[r8][0]);
                o[r8][1] = fmaf(p, v1, o[r8][1]);
                o[r8][2] = fmaf(p, v2, o[r8][2]);
                o[r8][3] = fmaf(p, v3, o[r8][3]);
            }
        }
    }

#pragma unroll
    for (int r8 = 0; r8 < 8; r8++) {
        int r = warp * 8 + r8;
        float inv = 1.f / lrow[r8];
        float* yb = Y + (size_t)(b * T_SZ + bi * 64 + r) * (NH * HD) + h * HD;
        yb[lane]      = rna_tf32(o[r8][0] * inv);
        yb[lane + 32] = rna_tf32(o[r8][1] * inv);
        yb[lane + 64] = rna_tf32(o[r8][2] * inv);
        yb[lane + 96] = rna_tf32(o[r8][3] * inv);
    }
}

// ---------------------------------------------------------------------------
extern "C" void kernel_launch(void* const* d_in, const int* in_sizes, int n_in,
                              void* d_out, int out_size) {
    const float* x  = (const float*)d_in[0];
    const float* wq = (const float*)d_in[1];
    const float* wk = (const float*)d_in[2];
    const float* wv = (const float*)d_in[3];
    const float* wo = (const float*)d_in[4];
    float* out = (float*)d_out;

    float *qp, *kp, *vp, *yp, *xr, *wqT, *wkT, *wvT, *woT;
    cudaGetSymbolAddress((void**)&qp,  g_q);
    cudaGetSymbolAddress((void**)&kp,  g_k);
    cudaGetSymbolAddress((void**)&vp,  g_v);
    cudaGetSymbolAddress((void**)&yp,  g_y);
    cudaGetSymbolAddress((void**)&xr,  g_xr);
    cudaGetSymbolAddress((void**)&wqT, g_wqT);
    cudaGetSymbolAddress((void**)&wkT, g_wkT);
    cudaGetSymbolAddress((void**)&wvT, g_wvT);
    cudaGetSymbolAddress((void**)&woT, g_woT);

    cudaFuncSetAttribute(gemm_mma, cudaFuncAttributeMaxDynamicSharedMemorySize, GEMM_SMEM);
    cudaFuncSetAttribute(flash_attn, cudaFuncAttributeMaxDynamicSharedMemorySize, 115200);

    dim3 tb(32, 8);
    transpose_rna<<<dim3(2048 / 32, 2048 / 32), tb>>>(wq, wqT, 2048, 2048);
    transpose_rna<<<dim3(512  / 32, 2048 / 32), tb>>>(wk, wkT, 2048, 512);
    transpose_rna<<<dim3(512  / 32, 2048 / 32), tb>>>(wv, wvT, 2048, 512);
    transpose_rna<<<dim3(2048 / 32, 2048 / 32), tb>>>(wo, woT, 2048, 2048);

    round_x<<<(MR * 2048 / 4 + 255) / 256, 256>>>(x, xr, MR * 2048 / 4);

    // QKV projections on tensor cores (mma.sync tf32)
    gemm_mma<<<dim3(2048 / BN, MR / BM), 256, GEMM_SMEM>>>(xr, wqT, qp, 2048);
    gemm_mma<<<dim3(512  / BN, MR / BM), 256, GEMM_SMEM>>>(xr, wkT, kp, 512);
    gemm_mma<<<dim3(512  / BN, MR / BM), 256, GEMM_SMEM>>>(xr, wvT, vp, 512);

    rope_inplace<<<(MR * NH  * 64 + 255) / 256, 256>>>(qp, NH);
    rope_inplace<<<(MR * NKV * 64 + 255) / 256, 256>>>(kp, NKV);

    flash_attn<<<dim3(T_SZ / 64, B_SZ * NH), 256, 115200>>>(qp, kp, vp, yp);

    // Output projection on tensor cores
    gemm_mma<<<dim3(2048 / BN, MR / BM), 256, GEMM_SMEM>>>(yp, woT, out, 2048);
}

// round 6
// speedup vs baseline: 3.4816x; 1.8611x over previous
#include <cuda_runtime.h>
#include <math.h>
#include <cstdint>

#define B_SZ 2
#define T_SZ 2048
#define NH   16
#define NKV  4
#define HD   128
#define MR   (B_SZ * T_SZ)   // 4096 rows
#define KC   2048            // inner dim of projection GEMMs

// ---------------- scratch (__device__ globals: allocation-free rule) --------
__device__ float g_q  [MR * NH  * HD];
__device__ float g_k  [MR * NKV * HD];
__device__ float g_v  [MR * NKV * HD];
__device__ float g_y  [MR * NH  * HD];
__device__ float g_xr [MR * 2048];       // x rounded to tf32
__device__ float g_wqT[2048 * 2048];     // W^T, tf32-rounded (row-major [N,K])
__device__ float g_wkT[512  * 2048];
__device__ float g_wvT[512  * 2048];
__device__ float g_woT[2048 * 2048];

// ---------------- PTX helpers (baseline compute_103-safe) -------------------
__device__ __forceinline__ float rna_tf32(float x) {
    uint32_t u;
    asm("cvt.rna.tf32.f32 %0, %1;" : "=r"(u) : "f"(x));
    return __uint_as_float(u);
}
__device__ __forceinline__ void cp16(uint32_t s, const void* g) {
    asm volatile("cp.async.cg.shared.global [%0], [%1], 16;" :: "r"(s), "l"(g));
}
__device__ __forceinline__ void cp_commit() {
    asm volatile("cp.async.commit_group;" ::: "memory");
}
template <int N> __device__ __forceinline__ void cp_wait() {
    asm volatile("cp.async.wait_group %0;" :: "n"(N) : "memory");
}
__device__ __forceinline__ void mma_tf32(float* c, const uint32_t* a, const uint32_t* b) {
    asm volatile(
        "mma.sync.aligned.m16n8k8.row.col.f32.tf32.tf32.f32 "
        "{%0,%1,%2,%3}, {%4,%5,%6,%7}, {%8,%9}, {%0,%1,%2,%3};"
        : "+f"(c[0]), "+f"(c[1]), "+f"(c[2]), "+f"(c[3])
        : "r"(a[0]), "r"(a[1]), "r"(a[2]), "r"(a[3]), "r"(b[0]), "r"(b[1]));
}

// ---------------------------------------------------------------------------
// tf32 mma.sync GEMM: C[M, N] = A[M, 2048] @ BT[N, 2048]^T  (A, BT row-major)
// 128x128x32 CTA tile, 256 threads (8 warps = 2m x 4n), warp tile 64x32.
// ---------------------------------------------------------------------------
#define BM 128
#define BN 128
#define BK 32
#define PAD 36
#define STG_FLOATS (2 * 128 * PAD)
#define GEMM_SMEM  (3 * STG_FLOATS * 4)

__device__ __forceinline__ void g_fill(uint32_t smb, int st, int ck, int tid,
                                       const float* Ab, const float* Bb) {
    uint32_t sa = smb + st * (STG_FLOATS * 4);
    uint32_t sb = sa + 128 * PAD * 4;
    const float* Ac = Ab + ck * BK;
    const float* Bc = Bb + ck * BK;
#pragma unroll
    for (int u = 0; u < 4; u++) {
        int idx = u * 256 + tid;
        int r = idx >> 3, c4 = (idx & 7) * 4;
        cp16(sa + (r * PAD + c4) * 4, Ac + (size_t)r * KC + c4);
    }
#pragma unroll
    for (int u = 0; u < 4; u++) {
        int idx = u * 256 + tid;
        int r = idx >> 3, c4 = (idx & 7) * 4;
        cp16(sb + (r * PAD + c4) * 4, Bc + (size_t)r * KC + c4);
    }
    cp_commit();
}

template <bool RNA>
__global__ void __launch_bounds__(256, 1)
gemm_mma(const float* __restrict__ A, const float* __restrict__ BT,
         float* __restrict__ C, int N) {
    extern __shared__ float smf[];
    uint32_t smb = (uint32_t)__cvta_generic_to_shared(smf);

    const int tid  = threadIdx.x;
    const int lane = tid & 31;
    const int warp = tid >> 5;
    const int wm   = (warp >> 2) * 64;
    const int wn   = (warp & 3) * 32;
    const int bm   = blockIdx.y * BM;
    const int bn   = blockIdx.x * BN;

    const float* Ab = A  + (size_t)bm * KC;
    const float* Bb = BT + (size_t)bn * KC;

    float acc[4][4][4];
#pragma unroll
    for (int i = 0; i < 4; i++)
#pragma unroll
        for (int j = 0; j < 4; j++)
#pragma unroll
            for (int r = 0; r < 4; r++) acc[i][j][r] = 0.f;

    g_fill(smb, 0, 0, tid, Ab, Bb);
    g_fill(smb, 1, 1, tid, Ab, Bb);

    const int lr = lane >> 2;
    const int lc = lane & 3;
    const int NCK = KC / BK;

    for (int i = 0; i < NCK; i++) {
        cp_wait<1>();
        __syncthreads();
        if (i + 2 < NCK) g_fill(smb, (i + 2) % 3, i + 2, tid, Ab, Bb);

        const float* As = smf + (i % 3) * STG_FLOATS;
        const float* Bs = As + 128 * PAD;

#pragma unroll
        for (int ks = 0; ks < 4; ks++) {
            uint32_t a[4][4], b[4][2];
#pragma unroll
            for (int mf = 0; mf < 4; mf++) {
                const float* p = As + (wm + mf * 16 + lr) * PAD + ks * 8 + lc;
                a[mf][0] = __float_as_uint(p[0]);
                a[mf][1] = __float_as_uint(p[8 * PAD]);
                a[mf][2] = __float_as_uint(p[4]);
                a[mf][3] = __float_as_uint(p[8 * PAD + 4]);
            }
#pragma unroll
            for (int nf = 0; nf < 4; nf++) {
                const float* q = Bs + (wn + nf * 8 + lr) * PAD + ks * 8 + lc;
                b[nf][0] = __float_as_uint(q[0]);
                b[nf][1] = __float_as_uint(q[4]);
            }
#pragma unroll
            for (int mf = 0; mf < 4; mf++)
#pragma unroll
                for (int nf = 0; nf < 4; nf++)
                    mma_tf32(acc[mf][nf], a[mf], b[nf]);
        }
        __syncthreads();
    }

#pragma unroll
    for (int mf = 0; mf < 4; mf++) {
        int row0 = bm + wm + mf * 16 + lr;
#pragma unroll
        for (int nf = 0; nf < 4; nf++) {
            int col = bn + wn + nf * 8 + lc * 2;
            float v0 = acc[mf][nf][0], v1 = acc[mf][nf][1];
            float v2 = acc[mf][nf][2], v3 = acc[mf][nf][3];
            if (RNA) { v0 = rna_tf32(v0); v1 = rna_tf32(v1);
                       v2 = rna_tf32(v2); v3 = rna_tf32(v3); }
            *(float2*)(C + (size_t)row0 * N + col)       = make_float2(v0, v1);
            *(float2*)(C + (size_t)(row0 + 8) * N + col) = make_float2(v2, v3);
        }
    }
}

// ---------------------------------------------------------------------------
// Weight transpose + tf32-round
// ---------------------------------------------------------------------------
__global__ void transpose_rna(const float* __restrict__ W, float* __restrict__ WT,
                              int K, int N) {
    __shared__ float t[32][33];
    int n0 = blockIdx.x * 32, k0 = blockIdx.y * 32;
    int tx = threadIdx.x, ty = threadIdx.y;
#pragma unroll
    for (int i = 0; i < 4; i++)
        t[ty + 8 * i][tx] = W[(size_t)(k0 + ty + 8 * i) * N + n0 + tx];
    __syncthreads();
#pragma unroll
    for (int i = 0; i < 4; i++)
        WT[(size_t)(n0 + ty + 8 * i) * K + k0 + tx] = rna_tf32(t[tx][ty + 8 * i]);
}

__global__ void round_x(const float* __restrict__ X, float* __restrict__ XR, int n4) {
    int i = blockIdx.x * blockDim.x + threadIdx.x;
    if (i >= n4) return;
    float4 v = ((const float4*)X)[i];
    v.x = rna_tf32(v.x); v.y = rna_tf32(v.y);
    v.z = rna_tf32(v.z); v.w = rna_tf32(v.w);
    ((float4*)XR)[i] = v;
}

// ---------------------------------------------------------------------------
// In-place RoPE; outputs rna-rounded to tf32 (feeds mma attention)
// ---------------------------------------------------------------------------
__global__ void rope_inplace(float* __restrict__ X, int nheads) {
    int idx = blockIdx.x * blockDim.x + threadIdx.x;
    int total = MR * 64 * nheads;
    if (idx >= total) return;
    int dp   = idx & 63;
    int rest = idx >> 6;
    int h    = rest % nheads;
    int bt   = rest / nheads;
    int t    = bt & (T_SZ - 1);

    float inv_freq = powf(10000.0f, -(float)(2 * dp) * (1.0f / 128.0f));
    float ang = (float)t * inv_freq;
    float sv, cv;
    sincosf(ang, &sv, &cv);

    float* p = X + (size_t)bt * (nheads * HD) + h * HD + dp;
    float x0 = p[0], x1 = p[64];
    p[0]  = rna_tf32(x0 * cv - x1 * sv);
    p[64] = rna_tf32(x1 * cv + x0 * sv);
}

// ---------------------------------------------------------------------------
// Tensor-core flash attention (tf32 mma.sync), causal, GQA.
// CTA: 128 queries; KV tiles of 64; 8 warps, each warp = 16 q rows x 64 keys.
// Smem (floats): Ps[128][68] @0, Ks[64][132] @8704, Vt[128][68] @17152.
// Q staged transiently at offset 8704 (overlaps Ks+Vt; freed before kv loop).
// ---------------------------------------------------------------------------
#define PPAD 68
#define KPAD 132
#define VPAD 68
#define FA_SMEM (25856 * 4)   // 103424 B

__global__ void __launch_bounds__(256, 1)
flash_mma(const float* __restrict__ Q, const float* __restrict__ K,
          const float* __restrict__ V, float* __restrict__ Y) {
    extern __shared__ float sm[];
    float* Ps = sm;
    float* Ks = sm + 8704;
    float* Vt = sm + 17152;
    float* Qs = sm + 8704;           // transient
    uint32_t smb = (uint32_t)__cvta_generic_to_shared(sm);

    const int bi  = gridDim.x - 1 - blockIdx.x;   // big tiles first (balance)
    const int bh  = blockIdx.y;
    const int b   = bh >> 4, h = bh & 15;
    const int kvh = h >> 2;
    const int tid = threadIdx.x;
    const int warp = tid >> 5, lane = tid & 31;
    const int lr = lane >> 2, lc = lane & 3;

    // stage Q tile (pre-rounded tf32 by rope) into smem, extract A-frags
    // 128 rows x 128 cols -> 32 cp16 per row, 4096 total, 16 iterations
    const float* qg = Q + (size_t)(b * T_SZ + bi * 128) * 2048 + h * 128;
#pragma unroll
    for (int it = 0; it < 16; it++) {
        int idx = it * 256 + tid;
        int r = idx >> 5, c = (idx & 31) * 4;
        cp16(smb + (8704 + r * KPAD + c) * 4, qg + (size_t)r * 2048 + c);
    }
    cp_commit();
    cp_wait<0>();
    __syncthreads();

    uint32_t qa[16][4];
#pragma unroll
    for (int ks = 0; ks < 16; ks++) {
        const float* p = Qs + (warp * 16 + lr) * KPAD + ks * 8 + lc;
        qa[ks][0] = __float_as_uint(p[0]);
        qa[ks][1] = __float_as_uint(p[8 * KPAD]);
        qa[ks][2] = __float_as_uint(p[4]);
        qa[ks][3] = __float_as_uint(p[8 * KPAD + 4]);
    }

    float o[16][4];
#pragma unroll
    for (int nf = 0; nf < 16; nf++)
        o[nf][0] = o[nf][1] = o[nf][2] = o[nf][3] = 0.f;
    float m0 = -1e30f, m1 = -1e30f, l0 = 0.f, l1 = 0.f;

    const float sc = 0.08838834764831845f;   // 1/sqrt(128)
    const int rlo = bi * 128 + warp * 16 + lr;
    const int jmax = 2 * bi + 1;

    for (int j = 0; j <= jmax; j++) {
        __syncthreads();   // prior tile's Ks/Vt fully consumed (and Qs, 1st iter)

        // K tile via cp.async: 64 rows x 128 cols -> 2048 cp16, 8 iterations
        const float* kg = K + (size_t)(b * T_SZ + j * 64) * 512 + kvh * 128;
#pragma unroll
        for (int it = 0; it < 8; it++) {
            int idx = it * 256 + tid;
            int r = idx >> 5, c = (idx & 31) * 4;
            cp16(smb + (8704 + r * KPAD + c) * 4, kg + (size_t)r * 512 + c);
        }
        cp_commit();

        // V tile transposed into Vt[d][tok] (tf32 from gemm RNA epilogue)
        {
            const float* vg = V + (size_t)(b * T_SZ + j * 64) * 512 + kvh * 128;
            int d  = (warp & 3) * 32 + lane;
            int t0 = (warp >> 2) * 4;
#pragma unroll
            for (int it = 0; it < 8; it++) {
                int t4 = t0 + it * 8;
                float4 vv;
                vv.x = vg[(size_t)(t4 + 0) * 512 + d];
                vv.y = vg[(size_t)(t4 + 1) * 512 + d];
                vv.z = vg[(size_t)(t4 + 2) * 512 + d];
                vv.w = vg[(size_t)(t4 + 3) * 512 + d];
                *(float4*)&Vt[d * VPAD + t4] = vv;
            }
        }
        cp_wait<0>();
        __syncthreads();

        // ---- S = Q K^T (warp: 16 x 64) ----
        float sa[8][4];
#pragma unroll
        for (int nf = 0; nf < 8; nf++)
            sa[nf][0] = sa[nf][1] = sa[nf][2] = sa[nf][3] = 0.f;
#pragma unroll
        for (int ks = 0; ks < 16; ks++) {
            uint32_t bf[8][2];
#pragma unroll
            for (int nf = 0; nf < 8; nf++) {
                const float* q = Ks + (nf * 8 + lr) * KPAD + ks * 8 + lc;
                bf[nf][0] = __float_as_uint(q[0]);
                bf[nf][1] = __float_as_uint(q[4]);
            }
#pragma unroll
            for (int nf = 0; nf < 8; nf++)
                mma_tf32(sa[nf], qa[ks], bf[nf]);
        }

        // ---- scale + causal mask ----
        const bool domask = (j >= 2 * bi);
#pragma unroll
        for (int nf = 0; nf < 8; nf++) {
            sa[nf][0] *= sc; sa[nf][1] *= sc;
            sa[nf][2] *= sc; sa[nf][3] *= sc;
            if (domask) {
                int c0 = j * 64 + nf * 8 + 2 * lc;
                if (c0 > rlo)         sa[nf][0] = -1e30f;
                if (c0 + 1 > rlo)     sa[nf][1] = -1e30f;
                if (c0 > rlo + 8)     sa[nf][2] = -1e30f;
                if (c0 + 1 > rlo + 8) sa[nf][3] = -1e30f;
            }
        }

        // ---- online softmax (2 rows per thread, quad-reduce) ----
        float mx0 = -1e30f, mx1 = -1e30f;
#pragma unroll
        for (int nf = 0; nf < 8; nf++) {
            mx0 = fmaxf(mx0, fmaxf(sa[nf][0], sa[nf][1]));
            mx1 = fmaxf(mx1, fmaxf(sa[nf][2], sa[nf][3]));
        }
        mx0 = fmaxf(mx0, __shfl_xor_sync(0xffffffffu, mx0, 1));
        mx0 = fmaxf(mx0, __shfl_xor_sync(0xffffffffu, mx0, 2));
        mx1 = fmaxf(mx1, __shfl_xor_sync(0xffffffffu, mx1, 1));
        mx1 = fmaxf(mx1, __shfl_xor_sync(0xffffffffu, mx1, 2));

        float mn0 = fmaxf(m0, mx0), mn1 = fmaxf(m1, mx1);
        float al0 = __expf(m0 - mn0), al1 = __expf(m1 - mn1);
        float s0 = 0.f, s1 = 0.f;
        float* pr0 = Ps + (warp * 16 + lr) * PPAD + 2 * lc;
#pragma unroll
        for (int nf = 0; nf < 8; nf++) {
            float p0 = __expf(sa[nf][0] - mn0);
            float p1 = __expf(sa[nf][1] - mn0);
            float p2 = __expf(sa[nf][2] - mn1);
            float p3 = __expf(sa[nf][3] - mn1);
            s0 += p0 + p1; s1 += p2 + p3;
            *(float2*)(pr0 + nf * 8)            = make_float2(rna_tf32(p0), rna_tf32(p1));
            *(float2*)(pr0 + 8 * PPAD + nf * 8) = make_float2(rna_tf32(p2), rna_tf32(p3));
        }
        s0 += __shfl_xor_sync(0xffffffffu, s0, 1);
        s0 += __shfl_xor_sync(0xffffffffu, s0, 2);
        s1 += __shfl_xor_sync(0xffffffffu, s1, 1);
        s1 += __shfl_xor_sync(0xffffffffu, s1, 2);
        l0 = l0 * al0 + s0; m0 = mn0;
        l1 = l1 * al1 + s1; m1 = mn1;
#pragma unroll
        for (int nf = 0; nf < 16; nf++) {
            o[nf][0] *= al0; o[nf][1] *= al0;
            o[nf][2] *= al1; o[nf][3] *= al1;
        }
        __syncwarp();   // Ps rows of this warp written; only this warp reads them

        // ---- O += P V (warp: 16 x 128) ----
#pragma unroll
        for (int ks = 0; ks < 8; ks++) {
            uint32_t pa[4];
            const float* pp = Ps + (warp * 16 + lr) * PPAD + ks * 8 + lc;
            pa[0] = __float_as_uint(pp[0]);
            pa[1] = __float_as_uint(pp[8 * PPAD]);
            pa[2] = __float_as_uint(pp[4]);
            pa[3] = __float_as_uint(pp[8 * PPAD + 4]);
#pragma unroll
            for (int nf = 0; nf < 16; nf++) {
                uint32_t bv[2];
                const float* vv = Vt + (nf * 8 + lr) * VPAD + ks * 8 + lc;
                bv[0] = __float_as_uint(vv[0]);
                bv[1] = __float_as_uint(vv[4]);
                mma_tf32(o[nf], pa, bv);
            }
        }
    }

    // ---- normalize + store (rna: feeds final tf32 GEMM) ----
    float inv0 = 1.f / l0, inv1 = 1.f / l1;
    float* y0 = Y + (size_t)(b * T_SZ + bi * 128 + warp * 16 + lr) * 2048 + h * 128 + 2 * lc;
#pragma unroll
    for (int nf = 0; nf < 16; nf++) {
        *(float2*)(y0 + nf * 8) =
            make_float2(rna_tf32(o[nf][0] * inv0), rna_tf32(o[nf][1] * inv0));
        *(float2*)(y0 + 8 * 2048 + nf * 8) =
            make_float2(rna_tf32(o[nf][2] * inv1), rna_tf32(o[nf][3] * inv1));
    }
}

// ---------------------------------------------------------------------------
extern "C" void kernel_launch(void* const* d_in, const int* in_sizes, int n_in,
                              void* d_out, int out_size) {
    const float* x  = (const float*)d_in[0];
    const float* wq = (const float*)d_in[1];
    const float* wk = (const float*)d_in[2];
    const float* wv = (const float*)d_in[3];
    const float* wo = (const float*)d_in[4];
    float* out = (float*)d_out;

    float *qp, *kp, *vp, *yp, *xr, *wqT, *wkT, *wvT, *woT;
    cudaGetSymbolAddress((void**)&qp,  g_q);
    cudaGetSymbolAddress((void**)&kp,  g_k);
    cudaGetSymbolAddress((void**)&vp,  g_v);
    cudaGetSymbolAddress((void**)&yp,  g_y);
    cudaGetSymbolAddress((void**)&xr,  g_xr);
    cudaGetSymbolAddress((void**)&wqT, g_wqT);
    cudaGetSymbolAddress((void**)&wkT, g_wkT);
    cudaGetSymbolAddress((void**)&wvT, g_wvT);
    cudaGetSymbolAddress((void**)&woT, g_woT);

    cudaFuncSetAttribute(gemm_mma<false>, cudaFuncAttributeMaxDynamicSharedMemorySize, GEMM_SMEM);
    cudaFuncSetAttribute(gemm_mma<true>,  cudaFuncAttributeMaxDynamicSharedMemorySize, GEMM_SMEM);
    cudaFuncSetAttribute(flash_mma, cudaFuncAttributeMaxDynamicSharedMemorySize, FA_SMEM);

    dim3 tb(32, 8);
    transpose_rna<<<dim3(2048 / 32, 2048 / 32), tb>>>(wq, wqT, 2048, 2048);
    transpose_rna<<<dim3(512  / 32, 2048 / 32), tb>>>(wk, wkT, 2048, 512);
    transpose_rna<<<dim3(512  / 32, 2048 / 32), tb>>>(wv, wvT, 2048, 512);
    transpose_rna<<<dim3(2048 / 32, 2048 / 32), tb>>>(wo, woT, 2048, 2048);

    round_x<<<(MR * 2048 / 4 + 255) / 256, 256>>>(x, xr, MR * 2048 / 4);

    // QKV projections (V output rna-rounded for the attention mma)
    gemm_mma<false><<<dim3(2048 / BN, MR / BM), 256, GEMM_SMEM>>>(xr, wqT, qp, 2048);
    gemm_mma<false><<<dim3(512  / BN, MR / BM), 256, GEMM_SMEM>>>(xr, wkT, kp, 512);
    gemm_mma<true ><<<dim3(512  / BN, MR / BM), 256, GEMM_SMEM>>>(xr, wvT, vp, 512);

    rope_inplace<<<(MR * NH  * 64 + 255) / 256, 256>>>(qp, NH);
    rope_inplace<<<(MR * NKV * 64 + 255) / 256, 256>>>(kp, NKV);

    // Tensor-core causal GQA flash attention
    flash_mma<<<dim3(T_SZ / 128, B_SZ * NH), 256, FA_SMEM>>>(qp, kp, vp, yp);

    // Output projection
    gemm_mma<false><<<dim3(2048 / BN, MR / BM), 256, GEMM_SMEM>>>(yp, woT, out, 2048);
}

// round 9
// speedup vs baseline: 3.6054x; 1.0355x over previous
#include <cuda_runtime.h>
#include <math.h>
#include <cstdint>

#define B_SZ 2
#define T_SZ 2048
#define NH   16
#define NKV  4
#define HD   128
#define MR   (B_SZ * T_SZ)   // 4096 rows
#define KC   2048            // inner dim of projection GEMMs

// ---------------- scratch (__device__ globals: allocation-free rule) --------
__device__ float g_q   [MR * NH  * HD];
__device__ float g_k   [MR * NKV * HD];
__device__ float g_v   [MR * NKV * HD];
__device__ float g_y   [MR * NH  * HD];   // k-permuted layout (feeds final GEMM)
__device__ float g_xr  [MR * 2048];       // x, tf32 + k-permuted
__device__ float g_wqkvT[3072 * 2048];    // [wq;wk;wv]^T, tf32 + k-permuted
__device__ float g_woT [2048 * 2048];     // wo^T, tf32 + k-permuted

// k-permutation within each 8-group: pos(k) = (k&~7) | ((k&3)<<1) | ((k>>2)&1)
// (so storage positions 2i, 2i+1 hold original cols i, i+4 -> v2 frag loads)

// ---------------- PTX helpers (baseline compute_103-safe) -------------------
__device__ __forceinline__ float rna_tf32(float x) {
    uint32_t u;
    asm("cvt.rna.tf32.f32 %0, %1;" : "=r"(u) : "f"(x));
    return __uint_as_float(u);
}
__device__ __forceinline__ void cp16(uint32_t s, const void* g) {
    asm volatile("cp.async.cg.shared.global [%0], [%1], 16;" :: "r"(s), "l"(g));
}
__device__ __forceinline__ void cp_commit() {
    asm volatile("cp.async.commit_group;" ::: "memory");
}
template <int N> __device__ __forceinline__ void cp_wait() {
    asm volatile("cp.async.wait_group %0;" :: "n"(N) : "memory");
}
__device__ __forceinline__ void mma_tf32(float* c, const uint32_t* a, const uint32_t* b) {
    asm volatile(
        "mma.sync.aligned.m16n8k8.row.col.f32.tf32.tf32.f32 "
        "{%0,%1,%2,%3}, {%4,%5,%6,%7}, {%8,%9}, {%0,%1,%2,%3};"
        : "+f"(c[0]), "+f"(c[1]), "+f"(c[2]), "+f"(c[3])
        : "r"(a[0]), "r"(a[1]), "r"(a[2]), "r"(a[3]), "r"(b[0]), "r"(b[1]));
}

// ---------------------------------------------------------------------------
// tf32 mma.sync GEMM, k-permuted operands: C[M,N] = A[M,2048] @ BT[N,2048]^T
// CTA tile 128(M) x 256(N) x 32(K); 256 thr, 8 warps (2m x 4n), warp 64x64.
// SPLIT: route output 64-col groups to q/k/v (v rna-rounded).
// ---------------------------------------------------------------------------
#define BM 128
#define BN 256
#define BK 32
#define PAD 36
#define STG_FLOATS ((BM + BN) * PAD)            // 13824 floats
#define GEMM_SMEM  (3 * STG_FLOATS * 4)         // 165888 B

__device__ __forceinline__ void g_fill(uint32_t smb, int st, int ck, int tid,
                                       const float* Ab, const float* Bb) {
    uint32_t sa = smb + st * (STG_FLOATS * 4);
    uint32_t sb = sa + BM * PAD * 4;
    const float* Ac = Ab + ck * BK;
    const float* Bc = Bb + ck * BK;
#pragma unroll
    for (int u = 0; u < 4; u++) {
        int idx = u * 256 + tid;
        int r = idx >> 3, c4 = (idx & 7) * 4;
        cp16(sa + (r * PAD + c4) * 4, Ac + (size_t)r * KC + c4);
    }
#pragma unroll
    for (int u = 0; u < 8; u++) {
        int idx = u * 256 + tid;
        int r = idx >> 3, c4 = (idx & 7) * 4;
        cp16(sb + (r * PAD + c4) * 4, Bc + (size_t)r * KC + c4);
    }
    cp_commit();
}

template <bool SPLIT>
__global__ void __launch_bounds__(256, 1)
gemm_mma(const float* __restrict__ A, const float* __restrict__ BT,
         float* __restrict__ C0, float* __restrict__ C1, float* __restrict__ C2,
         int N) {
    extern __shared__ float smf[];
    uint32_t smb = (uint32_t)__cvta_generic_to_shared(smf);

    const int tid  = threadIdx.x;
    const int lane = tid & 31;
    const int warp = tid >> 5;
    const int wm   = (warp >> 2) * 64;   // 0 or 64
    const int wn   = (warp & 3) * 64;    // 0,64,128,192
    const int bm   = blockIdx.y * BM;
    const int bn   = blockIdx.x * BN;

    const float* Ab = A  + (size_t)bm * KC;
    const float* Bb = BT + (size_t)bn * KC;

    float acc[4][8][4];
#pragma unroll
    for (int i = 0; i < 4; i++)
#pragma unroll
        for (int j = 0; j < 8; j++)
#pragma unroll
            for (int r = 0; r < 4; r++) acc[i][j][r] = 0.f;

    g_fill(smb, 0, 0, tid, Ab, Bb);
    g_fill(smb, 1, 1, tid, Ab, Bb);

    const int lr = lane >> 2;
    const int lc = lane & 3;
    const int NCK = KC / BK;

    for (int i = 0; i < NCK; i++) {
        cp_wait<1>();
        __syncthreads();
        if (i + 2 < NCK) g_fill(smb, (i + 2) % 3, i + 2, tid, Ab, Bb);

        const float* As = smf + (i % 3) * STG_FLOATS;
        const float* Bs = As + BM * PAD;

#pragma unroll
        for (int ks = 0; ks < 4; ks++) {
            uint32_t a[4][4], b[8][2];
#pragma unroll
            for (int mf = 0; mf < 4; mf++) {
                // permuted layout: v2 at 2*lc gives orig cols (lc, lc+4)
                float2 v0 = *(const float2*)(As + (wm + mf * 16 + lr) * PAD + ks * 8 + 2 * lc);
                float2 v1 = *(const float2*)(As + (wm + mf * 16 + lr + 8) * PAD + ks * 8 + 2 * lc);
                a[mf][0] = __float_as_uint(v0.x);
                a[mf][1] = __float_as_uint(v1.x);
                a[mf][2] = __float_as_uint(v0.y);
                a[mf][3] = __float_as_uint(v1.y);
            }
#pragma unroll
            for (int nf = 0; nf < 8; nf++) {
                float2 v = *(const float2*)(Bs + (wn + nf * 8 + lr) * PAD + ks * 8 + 2 * lc);
                b[nf][0] = __float_as_uint(v.x);
                b[nf][1] = __float_as_uint(v.y);
            }
#pragma unroll
            for (int mf = 0; mf < 4; mf++)
#pragma unroll
                for (int nf = 0; nf < 8; nf++)
                    mma_tf32(acc[mf][nf], a[mf], b[nf]);
        }
        __syncthreads();
    }

    // epilogue
    const int colbase = bn + wn;   // multiple of 64; q/k/v regions don't straddle
    float* dst; int ldc; int cb; bool dorna = false;
    if (!SPLIT)                 { dst = C0; ldc = N;    cb = colbase; }
    else if (colbase < 2048)    { dst = C0; ldc = 2048; cb = colbase; }
    else if (colbase < 2560)    { dst = C1; ldc = 512;  cb = colbase - 2048; }
    else                        { dst = C2; ldc = 512;  cb = colbase - 2560; dorna = true; }

#pragma unroll
    for (int mf = 0; mf < 4; mf++) {
        int row0 = bm + wm + mf * 16 + lr;
#pragma unroll
        for (int nf = 0; nf < 8; nf++) {
            int col = cb + nf * 8 + lc * 2;
            float v0 = acc[mf][nf][0], v1 = acc[mf][nf][1];
            float v2 = acc[mf][nf][2], v3 = acc[mf][nf][3];
            if (dorna) { v0 = rna_tf32(v0); v1 = rna_tf32(v1);
                         v2 = rna_tf32(v2); v3 = rna_tf32(v3); }
            *(float2*)(dst + (size_t)row0 * ldc + col)       = make_float2(v0, v1);
            *(float2*)(dst + (size_t)(row0 + 8) * ldc + col) = make_float2(v2, v3);
        }
    }
}

// ---------------------------------------------------------------------------
// Weight transpose + tf32-round + k-permute: WT[n][perm(k)] = rna(W[k][n])
// ---------------------------------------------------------------------------
__global__ void transpose_rna(const float* __restrict__ W, float* __restrict__ WT,
                              int K, int N) {
    __shared__ float t[32][33];
    int n0 = blockIdx.x * 32, k0 = blockIdx.y * 32;
    int tx = threadIdx.x, ty = threadIdx.y;
#pragma unroll
    for (int i = 0; i < 4; i++)
        t[ty + 8 * i][tx] = W[(size_t)(k0 + ty + 8 * i) * N + n0 + tx];
    __syncthreads();
    int k = k0 + tx;
    int kp = (k & ~7) | ((k & 3) << 1) | ((k >> 2) & 1);
#pragma unroll
    for (int i = 0; i < 4; i++)
        WT[(size_t)(n0 + ty + 8 * i) * K + kp] = rna_tf32(t[tx][ty + 8 * i]);
}

// x -> tf32, k-permuted within 8-groups
__global__ void round_x(const float* __restrict__ X, float* __restrict__ XR, int n4) {
    int i = blockIdx.x * blockDim.x + threadIdx.x;
    if (i >= n4) return;
    float4 v = ((const float4*)X)[i];
    int f0 = i * 4;
    int base = f0 & ~7;
    int off  = (f0 & 4) ? 1 : 0;
    XR[base + off + 0] = rna_tf32(v.x);
    XR[base + off + 2] = rna_tf32(v.y);
    XR[base + off + 4] = rna_tf32(v.z);
    XR[base + off + 6] = rna_tf32(v.w);
}

// ---------------------------------------------------------------------------
// In-place RoPE (natural layout; feeds attention), rna-rounded to tf32
// ---------------------------------------------------------------------------
__global__ void rope_inplace(float* __restrict__ X, int nheads) {
    int idx = blockIdx.x * blockDim.x + threadIdx.x;
    int total = MR * 64 * nheads;
    if (idx >= total) return;
    int dp   = idx & 63;
    int rest = idx >> 6;
    int h    = rest % nheads;
    int bt   = rest / nheads;
    int t    = bt & (T_SZ - 1);

    float inv_freq = powf(10000.0f, -(float)(2 * dp) * (1.0f / 128.0f));
    float ang = (float)t * inv_freq;
    float sv, cv;
    sincosf(ang, &sv, &cv);

    float* p = X + (size_t)bt * (nheads * HD) + h * HD + dp;
    float x0 = p[0], x1 = p[64];
    p[0]  = rna_tf32(x0 * cv - x1 * sv);
    p[64] = rna_tf32(x1 * cv + x0 * sv);
}

// ---------------------------------------------------------------------------
// Tensor-core flash attention (tf32 mma.sync), causal, GQA.  (unchanged core;
// y-epilogue now writes k-PERMUTED layout to feed the final GEMM)
// ---------------------------------------------------------------------------
#define PPAD 68
#define KPAD 132
#define VPAD 68
#define FA_SMEM (25856 * 4)   // 103424 B

__global__ void __launch_bounds__(256, 1)
flash_mma(const float* __restrict__ Q, const float* __restrict__ K,
          const float* __restrict__ V, float* __restrict__ Y) {
    extern __shared__ float sm[];
    float* Ps = sm;
    float* Ks = sm + 8704;
    float* Vt = sm + 17152;
    float* Qs = sm + 8704;           // transient
    uint32_t smb = (uint32_t)__cvta_generic_to_shared(sm);

    const int bi  = gridDim.x - 1 - blockIdx.x;
    const int bh  = blockIdx.y;
    const int b   = bh >> 4, h = bh & 15;
    const int kvh = h >> 2;
    const int tid = threadIdx.x;
    const int warp = tid >> 5, lane = tid & 31;
    const int lr = lane >> 2, lc = lane & 3;

    const float* qg = Q + (size_t)(b * T_SZ + bi * 128) * 2048 + h * 128;
#pragma unroll
    for (int it = 0; it < 16; it++) {
        int idx = it * 256 + tid;
        int r = idx >> 5, c = (idx & 31) * 4;
        cp16(smb + (8704 + r * KPAD + c) * 4, qg + (size_t)r * 2048 + c);
    }
    cp_commit();
    cp_wait<0>();
    __syncthreads();

    uint32_t qa[16][4];
#pragma unroll
    for (int ks = 0; ks < 16; ks++) {
        const float* p = Qs + (warp * 16 + lr) * KPAD + ks * 8 + lc;
        qa[ks][0] = __float_as_uint(p[0]);
        qa[ks][1] = __float_as_uint(p[8 * KPAD]);
        qa[ks][2] = __float_as_uint(p[4]);
        qa[ks][3] = __float_as_uint(p[8 * KPAD + 4]);
    }

    float o[16][4];
#pragma unroll
    for (int nf = 0; nf < 16; nf++)
        o[nf][0] = o[nf][1] = o[nf][2] = o[nf][3] = 0.f;
    float m0 = -1e30f, m1 = -1e30f, l0 = 0.f, l1 = 0.f;

    const float sc = 0.08838834764831845f;
    const int rlo = bi * 128 + warp * 16 + lr;
    const int jmax = 2 * bi + 1;

    for (int j = 0; j <= jmax; j++) {
        __syncthreads();

        const float* kg = K + (size_t)(b * T_SZ + j * 64) * 512 + kvh * 128;
#pragma unroll
        for (int it = 0; it < 8; it++) {
            int idx = it * 256 + tid;
            int r = idx >> 5, c = (idx & 31) * 4;
            cp16(smb + (8704 + r * KPAD + c) * 4, kg + (size_t)r * 512 + c);
        }
        cp_commit();

        {
            const float* vg = V + (size_t)(b * T_SZ + j * 64) * 512 + kvh * 128;
            int d  = (warp & 3) * 32 + lane;
            int t0 = (warp >> 2) * 4;
#pragma unroll
            for (int it = 0; it < 8; it++) {
                int t4 = t0 + it * 8;
                float4 vv;
                vv.x = vg[(size_t)(t4 + 0) * 512 + d];
                vv.y = vg[(size_t)(t4 + 1) * 512 + d];
                vv.z = vg[(size_t)(t4 + 2) * 512 + d];
                vv.w = vg[(size_t)(t4 + 3) * 512 + d];
                *(float4*)&Vt[d * VPAD + t4] = vv;
            }
        }
        cp_wait<0>();
        __syncthreads();

        float sa[8][4];
#pragma unroll
        for (int nf = 0; nf < 8; nf++)
            sa[nf][0] = sa[nf][1] = sa[nf][2] = sa[nf][3] = 0.f;
#pragma unroll
        for (int ks = 0; ks < 16; ks++) {
            uint32_t bf[8][2];
#pragma unroll
            for (int nf = 0; nf < 8; nf++) {
                const float* q = Ks + (nf * 8 + lr) * KPAD + ks * 8 + lc;
                bf[nf][0] = __float_as_uint(q[0]);
                bf[nf][1] = __float_as_uint(q[4]);
            }
#pragma unroll
            for (int nf = 0; nf < 8; nf++)
                mma_tf32(sa[nf], qa[ks], bf[nf]);
        }

        const bool domask = (j >= 2 * bi);
#pragma unroll
        for (int nf = 0; nf < 8; nf++) {
            sa[nf][0] *= sc; sa[nf][1] *= sc;
            sa[nf][2] *= sc; sa[nf][3] *= sc;
            if (domask) {
                int c0 = j * 64 + nf * 8 + 2 * lc;
                if (c0 > rlo)         sa[nf][0] = -1e30f;
                if (c0 + 1 > rlo)     sa[nf][1] = -1e30f;
                if (c0 > rlo + 8)     sa[nf][2] = -1e30f;
                if (c0 + 1 > rlo + 8) sa[nf][3] = -1e30f;
            }
        }

        float mx0 = -1e30f, mx1 = -1e30f;
#pragma unroll
        for (int nf = 0; nf < 8; nf++) {
            mx0 = fmaxf(mx0, fmaxf(sa[nf][0], sa[nf][1]));
            mx1 = fmaxf(mx1, fmaxf(sa[nf][2], sa[nf][3]));
        }
        mx0 = fmaxf(mx0, __shfl_xor_sync(0xffffffffu, mx0, 1));
        mx0 = fmaxf(mx0, __shfl_xor_sync(0xffffffffu, mx0, 2));
        mx1 = fmaxf(mx1, __shfl_xor_sync(0xffffffffu, mx1, 1));
        mx1 = fmaxf(mx1, __shfl_xor_sync(0xffffffffu, mx1, 2));

        float mn0 = fmaxf(m0, mx0), mn1 = fmaxf(m1, mx1);
        float al0 = __expf(m0 - mn0), al1 = __expf(m1 - mn1);
        float s0 = 0.f, s1 = 0.f;
        float* pr0 = Ps + (warp * 16 + lr) * PPAD + 2 * lc;
#pragma unroll
        for (int nf = 0; nf < 8; nf++) {
            float p0 = __expf(sa[nf][0] - mn0);
            float p1 = __expf(sa[nf][1] - mn0);
            float p2 = __expf(sa[nf][2] - mn1);
            float p3 = __expf(sa[nf][3] - mn1);
            s0 += p0 + p1; s1 += p2 + p3;
            *(float2*)(pr0 + nf * 8)            = make_float2(rna_tf32(p0), rna_tf32(p1));
            *(float2*)(pr0 + 8 * PPAD + nf * 8) = make_float2(rna_tf32(p2), rna_tf32(p3));
        }
        s0 += __shfl_xor_sync(0xffffffffu, s0, 1);
        s0 += __shfl_xor_sync(0xffffffffu, s0, 2);
        s1 += __shfl_xor_sync(0xffffffffu, s1, 1);
        s1 += __shfl_xor_sync(0xffffffffu, s1, 2);
        l0 = l0 * al0 + s0; m0 = mn0;
        l1 = l1 * al1 + s1; m1 = mn1;
#pragma unroll
        for (int nf = 0; nf < 16; nf++) {
            o[nf][0] *= al0; o[nf][1] *= al0;
            o[nf][2] *= al1; o[nf][3] *= al1;
        }
        __syncwarp();

#pragma unroll
        for (int ks = 0; ks < 8; ks++) {
            uint32_t pa[4];
            const float* pp = Ps + (warp * 16 + lr) * PPAD + ks * 8 + lc;
            pa[0] = __float_as_uint(pp[0]);
            pa[1] = __float_as_uint(pp[8 * PPAD]);
            pa[2] = __float_as_uint(pp[4]);
            pa[3] = __float_as_uint(pp[8 * PPAD + 4]);
#pragma unroll
            for (int nf = 0; nf < 16; nf++) {
                uint32_t bv[2];
                const float* vv = Vt + (nf * 8 + lr) * VPAD + ks * 8 + lc;
                bv[0] = __float_as_uint(vv[0]);
                bv[1] = __float_as_uint(vv[4]);
                mma_tf32(o[nf], pa, bv);
            }
        }
    }

    // ---- normalize + store, k-PERMUTED for the final GEMM's A operand ----
    // natural cols (2lc, 2lc+1) -> permuted positions (pc, pc+2)
    float inv0 = 1.f / l0, inv1 = 1.f / l1;
    int pc = (((2 * lc) & 3) << 1) | (lc >> 1);   // {0,4,1,5} for lc 0..3
    float* y0 = Y + (size_t)(b * T_SZ + bi * 128 + warp * 16 + lr) * 2048 + h * 128 + pc;
#pragma unroll
    for (int nf = 0; nf < 16; nf++) {
        y0[nf * 8]     = rna_tf32(o[nf][0] * inv0);
        y0[nf * 8 + 2] = rna_tf32(o[nf][1] * inv0);
        y0[8 * 2048 + nf * 8]     = rna_tf32(o[nf][2] * inv1);
        y0[8 * 2048 + nf * 8 + 2] = rna_tf32(o[nf][3] * inv1);
    }
}

// ---------------------------------------------------------------------------
extern "C" void kernel_launch(void* const* d_in, const int* in_sizes, int n_in,
                              void* d_out, int out_size) {
    const float* x  = (const float*)d_in[0];
    const float* wq = (const float*)d_in[1];
    const float* wk = (const float*)d_in[2];
    const float* wv = (const float*)d_in[3];
    const float* wo = (const float*)d_in[4];
    float* out = (float*)d_out;

    float *qp, *kp, *vp, *yp, *xr, *wqkvT, *woT;
    cudaGetSymbolAddress((void**)&qp,    g_q);
    cudaGetSymbolAddress((void**)&kp,    g_k);
    cudaGetSymbolAddress((void**)&vp,    g_v);
    cudaGetSymbolAddress((void**)&yp,    g_y);
    cudaGetSymbolAddress((void**)&xr,    g_xr);
    cudaGetSymbolAddress((void**)&wqkvT, g_wqkvT);
    cudaGetSymbolAddress((void**)&woT,   g_woT);

    cudaFuncSetAttribute(gemm_mma<false>, cudaFuncAttributeMaxDynamicSharedMemorySize, GEMM_SMEM);
    cudaFuncSetAttribute(gemm_mma<true>,  cudaFuncAttributeMaxDynamicSharedMemorySize, GEMM_SMEM);
    cudaFuncSetAttribute(flash_mma, cudaFuncAttributeMaxDynamicSharedMemorySize, FA_SMEM);

    dim3 tb(32, 8);
    transpose_rna<<<dim3(2048 / 32, 2048 / 32), tb>>>(wq, wqkvT,               2048, 2048);
    transpose_rna<<<dim3(512  / 32, 2048 / 32), tb>>>(wk, wqkvT + 2048 * 2048, 2048, 512);
    transpose_rna<<<dim3(512  / 32, 2048 / 32), tb>>>(wv, wqkvT + 2560 * 2048, 2048, 512);
    transpose_rna<<<dim3(2048 / 32, 2048 / 32), tb>>>(wo, woT,                 2048, 2048);

    round_x<<<(MR * 2048 / 4 + 255) / 256, 256>>>(x, xr, MR * 2048 / 4);

    // Fused QKV projection (N = 3072), epilogue routes to q/k/v (v rna'd)
    gemm_mma<true><<<dim3(3072 / BN, MR / BM), 256, GEMM_SMEM>>>(
        xr, wqkvT, qp, kp, vp, 3072);

    rope_inplace<<<(MR * NH  * 64 + 255) / 256, 256>>>(qp, NH);
    rope_inplace<<<(MR * NKV * 64 + 255) / 256, 256>>>(kp, NKV);

    // Tensor-core causal GQA flash attention (writes k-permuted y)
    flash_mma<<<dim3(T_SZ / 128, B_SZ * NH), 256, FA_SMEM>>>(qp, kp, vp, yp);

    // Output projection
    gemm_mma<false><<<dim3(2048 / BN, MR / BM), 256, GEMM_SMEM>>>(
        yp, woT, out, nullptr, nullptr, 2048);
}

// round 11
// speedup vs baseline: 5.1189x; 1.4198x over previous
#include <cuda_runtime.h>
#include <cuda_fp16.h>
#include <math.h>
#include <cstdint>

#define B_SZ 2
#define T_SZ 2048
#define NH   16
#define NKV  4
#define HD   128
#define MR   (B_SZ * T_SZ)   // 4096 rows
#define KC   2048            // inner dim (halves) of projection GEMMs

// ---------------- scratch (__device__ globals: allocation-free rule) --------
__device__ __half g_q   [MR * NH  * HD];   // head-dim pair-permuted (after rope)
__device__ __half g_k   [MR * NKV * HD];   // head-dim pair-permuted (after rope)
__device__ __half g_v   [MR * NKV * HD];   // natural
__device__ __half g_y   [MR * NH  * HD];   // pair-permuted (feeds final GEMM)
__device__ __half g_xh  [MR * 2048];       // x, fp16 + pair-permuted
__device__ __half g_wqkvT[3072 * 2048];    // [wq;wk;wv]^T, fp16 + pair-permuted
__device__ __half g_woT [2048 * 2048];     // wo^T, fp16 + pair-permuted

// pair-permutation within each 16-half k-group:
//   pair p (0..7) -> slot ((p&3)<<1)|(p>>2); element k -> k' below
__device__ __forceinline__ int pslot(int p) { return ((p & 3) << 1) | (p >> 2); }
__device__ __forceinline__ int kperm(int k) {
    return (k & ~15) | (pslot((k >> 1) & 7) << 1) | (k & 1);
}

// ---------------- PTX helpers (baseline compute_103-safe) -------------------
__device__ __forceinline__ void cp16(uint32_t s, const void* g) {
    asm volatile("cp.async.cg.shared.global [%0], [%1], 16;" :: "r"(s), "l"(g));
}
__device__ __forceinline__ void cp_commit() {
    asm volatile("cp.async.commit_group;" ::: "memory");
}
template <int N> __device__ __forceinline__ void cp_wait() {
    asm volatile("cp.async.wait_group %0;" :: "n"(N) : "memory");
}
// m16n8k16 fp16 mma, fp32 accum
__device__ __forceinline__ void mma_f16(float* c, const uint32_t* a, const uint32_t* b) {
    asm volatile(
        "mma.sync.aligned.m16n8k16.row.col.f32.f16.f16.f32 "
        "{%0,%1,%2,%3}, {%4,%5,%6,%7}, {%8,%9}, {%0,%1,%2,%3};"
        : "+f"(c[0]), "+f"(c[1]), "+f"(c[2]), "+f"(c[3])
        : "r"(a[0]), "r"(a[1]), "r"(a[2]), "r"(a[3]), "r"(b[0]), "r"(b[1]));
}

// ---------------------------------------------------------------------------
// fp16 mma GEMM: C[M,N] = A[M,2048] @ BT[N,2048]^T (both fp16, pair-permuted k)
// CTA 128(M) x 256(N) x 32(K halves); 256 thr, 8 warps (2m x 4n), warp 64x64.
// SPLIT: route 64-col groups to q/k (head-permuted) and v (natural), all fp16.
// ---------------------------------------------------------------------------
#define BM 128
#define BN 256
#define BK 32
#define PADH 40                               // halves per stage row
#define STG_HALVES ((BM + BN) * PADH)         // 15360
#define GEMM_SMEM  (3 * STG_HALVES * 2)       // 92160 B

__device__ __forceinline__ void g_fill(uint32_t smb, int st, int ck, int tid,
                                       const __half* Ab, const __half* Bb) {
    uint32_t sa = smb + st * (STG_HALVES * 2);
    uint32_t sb = sa + BM * PADH * 2;
    const __half* Ac = Ab + ck * BK;
    const __half* Bc = Bb + ck * BK;
#pragma unroll
    for (int u = 0; u < 2; u++) {           // A: 128 rows x 4 cp16
        int idx = u * 256 + tid;
        int r = idx >> 2, c8 = (idx & 3) * 8;
        cp16(sa + (r * PADH + c8) * 2, Ac + (size_t)r * KC + c8);
    }
#pragma unroll
    for (int u = 0; u < 4; u++) {           // B: 256 rows x 4 cp16
        int idx = u * 256 + tid;
        int r = idx >> 2, c8 = (idx & 3) * 8;
        cp16(sb + (r * PADH + c8) * 2, Bc + (size_t)r * KC + c8);
    }
    cp_commit();
}

template <bool SPLIT>
__global__ void __launch_bounds__(256, 1)
gemm_h(const __half* __restrict__ A, const __half* __restrict__ BT,
       float* __restrict__ Cf, __half* __restrict__ Cq,
       __half* __restrict__ Ck, __half* __restrict__ Cv, int N) {
    extern __shared__ __half smh[];
    uint32_t smb = (uint32_t)__cvta_generic_to_shared(smh);

    const int tid  = threadIdx.x;
    const int lane = tid & 31;
    const int warp = tid >> 5;
    const int wm   = (warp >> 2) * 64;
    const int wn   = (warp & 3) * 64;
    const int bm   = blockIdx.y * BM;
    const int bn   = blockIdx.x * BN;

    const __half* Ab = A  + (size_t)bm * KC;
    const __half* Bb = BT + (size_t)bn * KC;

    float acc[4][8][4];
#pragma unroll
    for (int i = 0; i < 4; i++)
#pragma unroll
        for (int j = 0; j < 8; j++)
#pragma unroll
            for (int r = 0; r < 4; r++) acc[i][j][r] = 0.f;

    g_fill(smb, 0, 0, tid, Ab, Bb);
    g_fill(smb, 1, 1, tid, Ab, Bb);

    const int lr = lane >> 2;
    const int lc = lane & 3;
    const int NCK = KC / BK;   // 64

    for (int i = 0; i < NCK; i++) {
        cp_wait<1>();
        __syncthreads();
        if (i + 2 < NCK) g_fill(smb, (i + 2) % 3, i + 2, tid, Ab, Bb);

        const __half* As = smh + (i % 3) * STG_HALVES;
        const __half* Bs = As + BM * PADH;

#pragma unroll
        for (int ks = 0; ks < 2; ks++) {      // two k16 chunks per BK=32
            uint32_t a[4][4], b[8][2];
#pragma unroll
            for (int mf = 0; mf < 4; mf++) {
                uint2 v0 = *(const uint2*)(As + (wm + mf * 16 + lr) * PADH + ks * 16 + 4 * lc);
                uint2 v1 = *(const uint2*)(As + (wm + mf * 16 + lr + 8) * PADH + ks * 16 + 4 * lc);
                a[mf][0] = v0.x; a[mf][1] = v1.x;
                a[mf][2] = v0.y; a[mf][3] = v1.y;
            }
#pragma unroll
            for (int nf = 0; nf < 8; nf++) {
                uint2 v = *(const uint2*)(Bs + (wn + nf * 8 + lr) * PADH + ks * 16 + 4 * lc);
                b[nf][0] = v.x; b[nf][1] = v.y;
            }
#pragma unroll
            for (int mf = 0; mf < 4; mf++)
#pragma unroll
                for (int nf = 0; nf < 8; nf++)
                    mma_f16(acc[mf][nf], a[mf], b[nf]);
        }
        __syncthreads();
    }

    // ---- epilogue ----
    const int colbase = bn + wn;    // multiple of 64
    if (!SPLIT) {
#pragma unroll
        for (int mf = 0; mf < 4; mf++) {
            int row0 = bm + wm + mf * 16 + lr;
#pragma unroll
            for (int nf = 0; nf < 8; nf++) {
                int col = colbase + nf * 8 + lc * 2;
                *(float2*)(Cf + (size_t)row0 * N + col) =
                    make_float2(acc[mf][nf][0], acc[mf][nf][1]);
                *(float2*)(Cf + (size_t)(row0 + 8) * N + col) =
                    make_float2(acc[mf][nf][2], acc[mf][nf][3]);
            }
        }
    } else {
        __half* dst; int ldc; int cb; bool perm;
        if (colbase < 2048)      { dst = Cq; ldc = 2048; cb = colbase;        perm = true; }
        else if (colbase < 2560) { dst = Ck; ldc = 512;  cb = colbase - 2048; perm = true; }
        else                     { dst = Cv; ldc = 512;  cb = colbase - 2560; perm = false; }
#pragma unroll
        for (int mf = 0; mf < 4; mf++) {
            int row0 = bm + wm + mf * 16 + lr;
#pragma unroll
            for (int nf = 0; nf < 8; nf++) {
                int col = cb + nf * 8 + lc * 2;
                int colw = col;
                if (perm) {
                    int hb = col & ~127, hc = col & 127;
                    colw = hb + (hc & ~15) + pslot((hc >> 1) & 7) * 2;
                }
                half2 v01 = __halves2half2(__float2half(acc[mf][nf][0]),
                                           __float2half(acc[mf][nf][1]));
                half2 v23 = __halves2half2(__float2half(acc[mf][nf][2]),
                                           __float2half(acc[mf][nf][3]));
                *(half2*)(dst + (size_t)row0 * ldc + colw)       = v01;
                *(half2*)(dst + (size_t)(row0 + 8) * ldc + colw) = v23;
            }
        }
    }
}

// ---------------------------------------------------------------------------
// Weight transpose + fp16 + pair-permute: WT[n][kperm(k)] = h(W[k][n])
// ---------------------------------------------------------------------------
__global__ void transpose_h(const float* __restrict__ W, __half* __restrict__ WT,
                            int K, int N) {
    __shared__ float t[32][33];
    int n0 = blockIdx.x * 32, k0 = blockIdx.y * 32;
    int tx = threadIdx.x, ty = threadIdx.y;
#pragma unroll
    for (int i = 0; i < 4; i++)
        t[ty + 8 * i][tx] = W[(size_t)(k0 + ty + 8 * i) * N + n0 + tx];
    __syncthreads();
    int kp = kperm(k0 + tx);
#pragma unroll
    for (int i = 0; i < 4; i++)
        WT[(size_t)(n0 + ty + 8 * i) * K + kp] = __float2half(t[tx][ty + 8 * i]);
}

// x -> fp16, pair-permuted
__global__ void conv_x(const float* __restrict__ X, __half* __restrict__ XH, int n4) {
    int i = blockIdx.x * blockDim.x + threadIdx.x;
    if (i >= n4) return;
    float4 v = ((const float4*)X)[i];
    int f0 = i * 4;                       // multiple of 4 -> pair index even
    int base = f0 & ~15;
    int p0 = (f0 >> 1) & 7;               // even
    int s0 = pslot(p0), s1 = pslot(p0 + 1);
    *(half2*)(XH + base + s0 * 2) = __halves2half2(__float2half(v.x), __float2half(v.y));
    *(half2*)(XH + base + s1 * 2) = __halves2half2(__float2half(v.z), __float2half(v.w));
}

// ---------------------------------------------------------------------------
// In-place RoPE on fp16 pair-permuted [B*T, nheads*128]
// ---------------------------------------------------------------------------
__global__ void rope_h(__half* __restrict__ X, int nheads) {
    int idx = blockIdx.x * blockDim.x + threadIdx.x;
    int total = MR * 64 * nheads;
    if (idx >= total) return;
    int dp   = idx & 63;
    int rest = idx >> 6;
    int h    = rest % nheads;
    int bt   = rest / nheads;
    int t    = bt & (T_SZ - 1);

    float inv_freq = powf(10000.0f, -(float)(2 * dp) * (1.0f / 128.0f));
    float ang = (float)t * inv_freq;
    float sv, cv;
    sincosf(ang, &sv, &cv);

    __half* p = X + (size_t)bt * (nheads * HD) + h * HD;
    int a0 = kperm(dp), a1 = kperm(dp + 64);
    float x0 = __half2float(p[a0]), x1 = __half2float(p[a1]);
    p[a0] = __float2half(x0 * cv - x1 * sv);
    p[a1] = __float2half(x1 * cv + x0 * sv);
}

// ---------------------------------------------------------------------------
// fp16 tensor-core flash attention (m16n8k16), causal, GQA.
// CTA: 128 queries; KV tiles of 64; 8 warps, warp = 16 q rows x all keys.
// Smem (halves): Ps[128][72] @0, Ks[64][136] @9216, Vt[128][72] @17920.
// Q staged transiently @9216 (region freed before kv loop). Total 54272 B.
// ---------------------------------------------------------------------------
#define PPADH 72
#define KPADH 136
#define VPADH 72
#define FA_SMEM (27136 * 2)

__global__ void __launch_bounds__(256, 1)
flash_h(const __half* __restrict__ Q, const __half* __restrict__ K,
        const __half* __restrict__ V, __half* __restrict__ Y) {
    extern __shared__ __half smh[];
    __half* Ps = smh;
    __half* Ks = smh + 9216;
    __half* Vt = smh + 17920;
    __half* Qs = smh + 9216;           // transient
    uint32_t smb = (uint32_t)__cvta_generic_to_shared(smh);

    const int bi  = gridDim.x - 1 - blockIdx.x;   // big tiles first
    const int bh  = blockIdx.y;
    const int b   = bh >> 4, h = bh & 15;
    const int kvh = h >> 2;
    const int tid = threadIdx.x;
    const int warp = tid >> 5, lane = tid & 31;
    const int lr = lane >> 2, lc = lane & 3;

    // stage Q tile (fp16, head-dim pair-permuted by rope): 128 x 128 halves
    const __half* qg = Q + (size_t)(b * T_SZ + bi * 128) * 2048 + h * 128;
#pragma unroll
    for (int it = 0; it < 8; it++) {
        int idx = it * 256 + tid;
        int r = idx >> 4, c8 = (idx & 15) * 8;
        cp16(smb + (9216 + r * KPADH + c8) * 2, qg + (size_t)r * 2048 + c8);
    }
    cp_commit();
    cp_wait<0>();
    __syncthreads();

    uint32_t qa[8][4];
#pragma unroll
    for (int ck = 0; ck < 8; ck++) {
        uint2 v0 = *(const uint2*)(Qs + (warp * 16 + lr) * KPADH + ck * 16 + 4 * lc);
        uint2 v1 = *(const uint2*)(Qs + (warp * 16 + lr + 8) * KPADH + ck * 16 + 4 * lc);
        qa[ck][0] = v0.x; qa[ck][1] = v1.x;
        qa[ck][2] = v0.y; qa[ck][3] = v1.y;
    }

    float o[16][4];
#pragma unroll
    for (int nf = 0; nf < 16; nf++)
        o[nf][0] = o[nf][1] = o[nf][2] = o[nf][3] = 0.f;
    float m0 = -1e30f, m1 = -1e30f, l0 = 0.f, l1 = 0.f;

    const float sc = 0.08838834764831845f;   // 1/sqrt(128)
    const int rlo = bi * 128 + warp * 16 + lr;
    const int jmax = 2 * bi + 1;

    for (int j = 0; j <= jmax; j++) {
        __syncthreads();   // prior tile fully consumed (and Qs, 1st iter)

        // K tile: 64 x 128 halves (pair-permuted head dim)
        const __half* kg = K + (size_t)(b * T_SZ + j * 64) * 512 + kvh * 128;
#pragma unroll
        for (int it = 0; it < 4; it++) {
            int idx = it * 256 + tid;
            int r = idx >> 4, c8 = (idx & 15) * 8;
            cp16(smb + (9216 + r * KPADH + c8) * 2, kg + (size_t)r * 512 + c8);
        }
        cp_commit();

        // V tile transposed into Vt[d][t] with t pair-permuted
        {
            const __half* vg = V + (size_t)(b * T_SZ + j * 64) * 512 + kvh * 128;
            int d  = (warp & 3) * 32 + lane;
            int t0 = (warp >> 2) * 4;
#pragma unroll
            for (int it = 0; it < 8; it++) {
                int t4 = t0 + it * 8;   // multiple of 4
                __half v0 = vg[(size_t)(t4 + 0) * 512 + d];
                __half v1 = vg[(size_t)(t4 + 1) * 512 + d];
                __half v2 = vg[(size_t)(t4 + 2) * 512 + d];
                __half v3 = vg[(size_t)(t4 + 3) * 512 + d];
                int p = t4 >> 1;                       // even pair
                int chb = (p >> 3) * 16;
                *(half2*)(Vt + d * VPADH + chb + pslot(p & 7) * 2) =
                    __halves2half2(v0, v1);
                *(half2*)(Vt + d * VPADH + chb + pslot((p + 1) & 7) * 2) =
                    __halves2half2(v2, v3);
            }
        }
        cp_wait<0>();
        __syncthreads();

        // ---- S = Q K^T (warp: 16 x 64), 8 k16 chunks ----
        float sa[8][4];
#pragma unroll
        for (int nf = 0; nf < 8; nf++)
            sa[nf][0] = sa[nf][1] = sa[nf][2] = sa[nf][3] = 0.f;
#pragma unroll
        for (int ck = 0; ck < 8; ck++) {
            uint32_t bf[8][2];
#pragma unroll
            for (int nf = 0; nf < 8; nf++) {
                uint2 v = *(const uint2*)(Ks + (nf * 8 + lr) * KPADH + ck * 16 + 4 * lc);
                bf[nf][0] = v.x; bf[nf][1] = v.y;
            }
#pragma unroll
            for (int nf = 0; nf < 8; nf++)
                mma_f16(sa[nf], qa[ck], bf[nf]);
        }

        // ---- scale + causal mask ----
        const bool domask = (j >= 2 * bi);
#pragma unroll
        for (int nf = 0; nf < 8; nf++) {
            sa[nf][0] *= sc; sa[nf][1] *= sc;
            sa[nf][2] *= sc; sa[nf][3] *= sc;
            if (domask) {
                int c0 = j * 64 + nf * 8 + 2 * lc;
                if (c0 > rlo)         sa[nf][0] = -1e30f;
                if (c0 + 1 > rlo)     sa[nf][1] = -1e30f;
                if (c0 > rlo + 8)     sa[nf][2] = -1e30f;
                if (c0 + 1 > rlo + 8) sa[nf][3] = -1e30f;
            }
        }

        // ---- online softmax (2 rows/thread, quad reduce) ----
        float mx0 = -1e30f, mx1 = -1e30f;
#pragma unroll
        for (int nf = 0; nf < 8; nf++) {
            mx0 = fmaxf(mx0, fmaxf(sa[nf][0], sa[nf][1]));
            mx1 = fmaxf(mx1, fmaxf(sa[nf][2], sa[nf][3]));
        }
        mx0 = fmaxf(mx0, __shfl_xor_sync(0xffffffffu, mx0, 1));
        mx0 = fmaxf(mx0, __shfl_xor_sync(0xffffffffu, mx0, 2));
        mx1 = fmaxf(mx1, __shfl_xor_sync(0xffffffffu, mx1, 1));
        mx1 = fmaxf(mx1, __shfl_xor_sync(0xffffffffu, mx1, 2));

        float mn0 = fmaxf(m0, mx0), mn1 = fmaxf(m1, mx1);
        float al0 = __expf(m0 - mn0), al1 = __expf(m1 - mn1);
        float s0 = 0.f, s1 = 0.f;
        // P -> smem fp16, pair-permuted: pair (nf*4+lc) -> slot (lc<<1)|(nf&1)
        __half* pr0 = Ps + (warp * 16 + lr) * PPADH;
        __half* pr1 = pr0 + 8 * PPADH;
#pragma unroll
        for (int nf = 0; nf < 8; nf++) {
            float p0 = __expf(sa[nf][0] - mn0);
            float p1 = __expf(sa[nf][1] - mn0);
            float p2 = __expf(sa[nf][2] - mn1);
            float p3 = __expf(sa[nf][3] - mn1);
            s0 += p0 + p1; s1 += p2 + p3;
            int off = (nf >> 1) * 16 + (((lc << 1) | (nf & 1)) << 1);
            *(half2*)(pr0 + off) = __halves2half2(__float2half(p0), __float2half(p1));
            *(half2*)(pr1 + off) = __halves2half2(__float2half(p2), __float2half(p3));
        }
        s0 += __shfl_xor_sync(0xffffffffu, s0, 1);
        s0 += __shfl_xor_sync(0xffffffffu, s0, 2);
        s1 += __shfl_xor_sync(0xffffffffu, s1, 1);
        s1 += __shfl_xor_sync(0xffffffffu, s1, 2);
        l0 = l0 * al0 + s0; m0 = mn0;
        l1 = l1 * al1 + s1; m1 = mn1;
#pragma unroll
        for (int nf = 0; nf < 16; nf++) {
            o[nf][0] *= al0; o[nf][1] *= al0;
            o[nf][2] *= al1; o[nf][3] *= al1;
        }
        __syncwarp();   // Ps rows of this warp written; only this warp reads

        // ---- O += P V (warp: 16 x 128), 4 k16 chunks over t ----
#pragma unroll
        for (int ck = 0; ck < 4; ck++) {
            uint32_t pa[4];
            uint2 u0 = *(const uint2*)(Ps + (warp * 16 + lr) * PPADH + ck * 16 + 4 * lc);
            uint2 u1 = *(const uint2*)(Ps + (warp * 16 + lr + 8) * PPADH + ck * 16 + 4 * lc);
            pa[0] = u0.x; pa[1] = u1.x; pa[2] = u0.y; pa[3] = u1.y;
#pragma unroll
            for (int nf = 0; nf < 16; nf++) {
                uint2 bv = *(const uint2*)(Vt + (nf * 8 + lr) * VPADH + ck * 16 + 4 * lc);
                uint32_t bb[2] = {bv.x, bv.y};
                mma_f16(o[nf], pa, bb);
            }
        }
    }

    // ---- normalize + store y fp16, pair-permuted (feeds final GEMM) ----
    float inv0 = 1.f / l0, inv1 = 1.f / l1;
    __half* y0 = Y + (size_t)(b * T_SZ + bi * 128 + warp * 16 + lr) * 2048 + h * 128;
    __half* y1 = y0 + 8 * 2048;
#pragma unroll
    for (int nf = 0; nf < 16; nf++) {
        int hc = nf * 8 + 2 * lc;
        int colw = (hc & ~15) + pslot((hc >> 1) & 7) * 2;
        *(half2*)(y0 + colw) = __halves2half2(__float2half(o[nf][0] * inv0),
                                              __float2half(o[nf][1] * inv0));
        *(half2*)(y1 + colw) = __halves2half2(__float2half(o[nf][2] * inv1),
                                              __float2half(o[nf][3] * inv1));
    }
}

// ---------------------------------------------------------------------------
extern "C" void kernel_launch(void* const* d_in, const int* in_sizes, int n_in,
                              void* d_out, int out_size) {
    const float* x  = (const float*)d_in[0];
    const float* wq = (const float*)d_in[1];
    const float* wk = (const float*)d_in[2];
    const float* wv = (const float*)d_in[3];
    const float* wo = (const float*)d_in[4];
    float* out = (float*)d_out;

    __half *qp, *kp, *vp, *yp, *xh, *wqkvT, *woT;
    cudaGetSymbolAddress((void**)&qp,    g_q);
    cudaGetSymbolAddress((void**)&kp,    g_k);
    cudaGetSymbolAddress((void**)&vp,    g_v);
    cudaGetSymbolAddress((void**)&yp,    g_y);
    cudaGetSymbolAddress((void**)&xh,    g_xh);
    cudaGetSymbolAddress((void**)&wqkvT, g_wqkvT);
    cudaGetSymbolAddress((void**)&woT,   g_woT);

    cudaFuncSetAttribute(gemm_h<false>, cudaFuncAttributeMaxDynamicSharedMemorySize, GEMM_SMEM);
    cudaFuncSetAttribute(gemm_h<true>,  cudaFuncAttributeMaxDynamicSharedMemorySize, GEMM_SMEM);
    cudaFuncSetAttribute(flash_h, cudaFuncAttributeMaxDynamicSharedMemorySize, FA_SMEM);

    dim3 tb(32, 8);
    transpose_h<<<dim3(2048 / 32, 2048 / 32), tb>>>(wq, wqkvT,               2048, 2048);
    transpose_h<<<dim3(512  / 32, 2048 / 32), tb>>>(wk, wqkvT + 2048 * 2048, 2048, 512);
    transpose_h<<<dim3(512  / 32, 2048 / 32), tb>>>(wv, wqkvT + 2560 * 2048, 2048, 512);
    transpose_h<<<dim3(2048 / 32, 2048 / 32), tb>>>(wo, woT,                 2048, 2048);

    conv_x<<<(MR * 2048 / 4 + 255) / 256, 256>>>(x, xh, MR * 2048 / 4);

    // Fused QKV projection (N = 3072); q,k head-permuted fp16; v natural fp16
    gemm_h<true><<<dim3(3072 / BN, MR / BM), 256, GEMM_SMEM>>>(
        xh, wqkvT, nullptr, qp, kp, vp, 3072);

    rope_h<<<(MR * NH  * 64 + 255) / 256, 256>>>(qp, NH);
    rope_h<<<(MR * NKV * 64 + 255) / 256, 256>>>(kp, NKV);

    // fp16 tensor-core causal GQA flash attention
    flash_h<<<dim3(T_SZ / 128, B_SZ * NH), 256, FA_SMEM>>>(qp, kp, vp, yp);

    // Output projection (fp32 out)
    gemm_h<false><<<dim3(2048 / BN, MR / BM), 256, GEMM_SMEM>>>(
        yp, woT, out, nullptr, nullptr, nullptr, 2048);
}

// round 12
// speedup vs baseline: 5.2998x; 1.0353x over previous
#include <cuda_runtime.h>
#include <cuda_fp16.h>
#include <math.h>
#include <cstdint>

#define B_SZ 2
#define T_SZ 2048
#define NH   16
#define NKV  4
#define HD   128
#define MR   (B_SZ * T_SZ)   // 4096 rows
#define KC   2048            // inner dim (halves) of projection GEMMs

// ---------------- scratch (__device__ globals: allocation-free rule) --------
__device__ __half g_q   [MR * NH  * HD];   // head-dim pair-permuted (after rope)
__device__ __half g_k   [MR * NKV * HD];   // head-dim pair-permuted (after rope)
__device__ __half g_v   [MR * NKV * HD];   // natural
__device__ __half g_y   [MR * NH  * HD];   // pair-permuted (feeds final GEMM)
__device__ __half g_xh  [MR * 2048];       // x, fp16 + pair-permuted
__device__ __half g_wqkvT[3072 * 2048];    // [wq;wk;wv]^T, fp16 + pair-permuted
__device__ __half g_woT [2048 * 2048];     // wo^T, fp16 + pair-permuted

// pair-permutation within each 16-half k-group:
//   pair p (0..7) -> slot ((p&3)<<1)|(p>>2); element k -> k' below
__device__ __forceinline__ int pslot(int p) { return ((p & 3) << 1) | (p >> 2); }
__device__ __forceinline__ int kperm(int k) {
    return (k & ~15) | (pslot((k >> 1) & 7) << 1) | (k & 1);
}

// ---------------- PTX helpers (baseline compute_103-safe) -------------------
__device__ __forceinline__ void cp16(uint32_t s, const void* g) {
    asm volatile("cp.async.cg.shared.global [%0], [%1], 16;" :: "r"(s), "l"(g));
}
__device__ __forceinline__ void cp_commit() {
    asm volatile("cp.async.commit_group;" ::: "memory");
}
template <int N> __device__ __forceinline__ void cp_wait() {
    asm volatile("cp.async.wait_group %0;" :: "n"(N) : "memory");
}
// m16n8k16 fp16 mma, fp32 accum
__device__ __forceinline__ void mma_f16(float* c, const uint32_t* a, const uint32_t* b) {
    asm volatile(
        "mma.sync.aligned.m16n8k16.row.col.f32.f16.f16.f32 "
        "{%0,%1,%2,%3}, {%4,%5,%6,%7}, {%8,%9}, {%0,%1,%2,%3};"
        : "+f"(c[0]), "+f"(c[1]), "+f"(c[2]), "+f"(c[3])
        : "r"(a[0]), "r"(a[1]), "r"(a[2]), "r"(a[3]), "r"(b[0]), "r"(b[1]));
}
__device__ __forceinline__ uint32_t f2h2(float a, float b) {
    half2 h = __floats2half2_rn(a, b);
    return *(uint32_t*)&h;
}

// ---------------------------------------------------------------------------
// fp16 mma GEMM: C[M,N] = A[M,2048] @ BT[N,2048]^T (both fp16, pair-permuted k)
// CTA 128(M) x 256(N) x 32(K halves); 256 thr, 8 warps (2m x 4n), warp 64x64.
// SPLIT: route 64-col groups to q/k (head-permuted) and v (natural), all fp16.
// ---------------------------------------------------------------------------
#define BM 128
#define BN 256
#define BK 32
#define PADH 40                               // halves per stage row
#define STG_HALVES ((BM + BN) * PADH)         // 15360
#define GEMM_SMEM  (3 * STG_HALVES * 2)       // 92160 B

__device__ __forceinline__ void g_fill(uint32_t smb, int st, int ck, int tid,
                                       const __half* Ab, const __half* Bb) {
    uint32_t sa = smb + st * (STG_HALVES * 2);
    uint32_t sb = sa + BM * PADH * 2;
    const __half* Ac = Ab + ck * BK;
    const __half* Bc = Bb + ck * BK;
#pragma unroll
    for (int u = 0; u < 2; u++) {           // A: 128 rows x 4 cp16
        int idx = u * 256 + tid;
        int r = idx >> 2, c8 = (idx & 3) * 8;
        cp16(sa + (r * PADH + c8) * 2, Ac + (size_t)r * KC + c8);
    }
#pragma unroll
    for (int u = 0; u < 4; u++) {           // B: 256 rows x 4 cp16
        int idx = u * 256 + tid;
        int r = idx >> 2, c8 = (idx & 3) * 8;
        cp16(sb + (r * PADH + c8) * 2, Bc + (size_t)r * KC + c8);
    }
    cp_commit();
}

template <bool SPLIT>
__global__ void __launch_bounds__(256, 1)
gemm_h(const __half* __restrict__ A, const __half* __restrict__ BT,
       float* __restrict__ Cf, __half* __restrict__ Cq,
       __half* __restrict__ Ck, __half* __restrict__ Cv, int N) {
    extern __shared__ __half smh[];
    uint32_t smb = (uint32_t)__cvta_generic_to_shared(smh);

    const int tid  = threadIdx.x;
    const int lane = tid & 31;
    const int warp = tid >> 5;
    const int wm   = (warp >> 2) * 64;
    const int wn   = (warp & 3) * 64;
    const int bm   = blockIdx.y * BM;
    const int bn   = blockIdx.x * BN;

    const __half* Ab = A  + (size_t)bm * KC;
    const __half* Bb = BT + (size_t)bn * KC;

    float acc[4][8][4];
#pragma unroll
    for (int i = 0; i < 4; i++)
#pragma unroll
        for (int j = 0; j < 8; j++)
#pragma unroll
            for (int r = 0; r < 4; r++) acc[i][j][r] = 0.f;

    g_fill(smb, 0, 0, tid, Ab, Bb);
    g_fill(smb, 1, 1, tid, Ab, Bb);

    const int lr = lane >> 2;
    const int lc = lane & 3;
    const int NCK = KC / BK;   // 64

    for (int i = 0; i < NCK; i++) {
        cp_wait<1>();
        __syncthreads();
        if (i + 2 < NCK) g_fill(smb, (i + 2) % 3, i + 2, tid, Ab, Bb);

        const __half* As = smh + (i % 3) * STG_HALVES;
        const __half* Bs = As + BM * PADH;

#pragma unroll
        for (int ks = 0; ks < 2; ks++) {      // two k16 chunks per BK=32
            uint32_t a[4][4], b[8][2];
#pragma unroll
            for (int mf = 0; mf < 4; mf++) {
                uint2 v0 = *(const uint2*)(As + (wm + mf * 16 + lr) * PADH + ks * 16 + 4 * lc);
                uint2 v1 = *(const uint2*)(As + (wm + mf * 16 + lr + 8) * PADH + ks * 16 + 4 * lc);
                a[mf][0] = v0.x; a[mf][1] = v1.x;
                a[mf][2] = v0.y; a[mf][3] = v1.y;
            }
#pragma unroll
            for (int nf = 0; nf < 8; nf++) {
                uint2 v = *(const uint2*)(Bs + (wn + nf * 8 + lr) * PADH + ks * 16 + 4 * lc);
                b[nf][0] = v.x; b[nf][1] = v.y;
            }
#pragma unroll
            for (int mf = 0; mf < 4; mf++)
#pragma unroll
                for (int nf = 0; nf < 8; nf++)
                    mma_f16(acc[mf][nf], a[mf], b[nf]);
        }
        __syncthreads();
    }

    // ---- epilogue ----
    const int colbase = bn + wn;    // multiple of 64
    if (!SPLIT) {
#pragma unroll
        for (int mf = 0; mf < 4; mf++) {
            int row0 = bm + wm + mf * 16 + lr;
#pragma unroll
            for (int nf = 0; nf < 8; nf++) {
                int col = colbase + nf * 8 + lc * 2;
                *(float2*)(Cf + (size_t)row0 * N + col) =
                    make_float2(acc[mf][nf][0], acc[mf][nf][1]);
                *(float2*)(Cf + (size_t)(row0 + 8) * N + col) =
                    make_float2(acc[mf][nf][2], acc[mf][nf][3]);
            }
        }
    } else {
        __half* dst; int ldc; int cb; bool perm;
        if (colbase < 2048)      { dst = Cq; ldc = 2048; cb = colbase;        perm = true; }
        else if (colbase < 2560) { dst = Ck; ldc = 512;  cb = colbase - 2048; perm = true; }
        else                     { dst = Cv; ldc = 512;  cb = colbase - 2560; perm = false; }
#pragma unroll
        for (int mf = 0; mf < 4; mf++) {
            int row0 = bm + wm + mf * 16 + lr;
#pragma unroll
            for (int nf = 0; nf < 8; nf++) {
                int col = cb + nf * 8 + lc * 2;
                int colw = col;
                if (perm) {
                    int hb = col & ~127, hc = col & 127;
                    colw = hb + (hc & ~15) + pslot((hc >> 1) & 7) * 2;
                }
                half2 v01 = __halves2half2(__float2half(acc[mf][nf][0]),
                                           __float2half(acc[mf][nf][1]));
                half2 v23 = __halves2half2(__float2half(acc[mf][nf][2]),
                                           __float2half(acc[mf][nf][3]));
                *(half2*)(dst + (size_t)row0 * ldc + colw)       = v01;
                *(half2*)(dst + (size_t)(row0 + 8) * ldc + colw) = v23;
            }
        }
    }
}

// ---------------------------------------------------------------------------
// Weight transpose + fp16 + pair-permute: WT[n][kperm(k)] = h(W[k][n])
// ---------------------------------------------------------------------------
__global__ void transpose_h(const float* __restrict__ W, __half* __restrict__ WT,
                            int K, int N) {
    __shared__ float t[32][33];
    int n0 = blockIdx.x * 32, k0 = blockIdx.y * 32;
    int tx = threadIdx.x, ty = threadIdx.y;
#pragma unroll
    for (int i = 0; i < 4; i++)
        t[ty + 8 * i][tx] = W[(size_t)(k0 + ty + 8 * i) * N + n0 + tx];
    __syncthreads();
    int kp = kperm(k0 + tx);
#pragma unroll
    for (int i = 0; i < 4; i++)
        WT[(size_t)(n0 + ty + 8 * i) * K + kp] = __float2half(t[tx][ty + 8 * i]);
}

// x -> fp16, pair-permuted
__global__ void conv_x(const float* __restrict__ X, __half* __restrict__ XH, int n4) {
    int i = blockIdx.x * blockDim.x + threadIdx.x;
    if (i >= n4) return;
    float4 v = ((const float4*)X)[i];
    int f0 = i * 4;                       // multiple of 4 -> pair index even
    int base = f0 & ~15;
    int p0 = (f0 >> 1) & 7;               // even
    int s0 = pslot(p0), s1 = pslot(p0 + 1);
    *(half2*)(XH + base + s0 * 2) = __halves2half2(__float2half(v.x), __float2half(v.y));
    *(half2*)(XH + base + s1 * 2) = __halves2half2(__float2half(v.z), __float2half(v.w));
}

// ---------------------------------------------------------------------------
// In-place RoPE on fp16 pair-permuted [B*T, nheads*128]
// ---------------------------------------------------------------------------
__global__ void rope_h(__half* __restrict__ X, int nheads) {
    int idx = blockIdx.x * blockDim.x + threadIdx.x;
    int total = MR * 64 * nheads;
    if (idx >= total) return;
    int dp   = idx & 63;
    int rest = idx >> 6;
    int h    = rest % nheads;
    int bt   = rest / nheads;
    int t    = bt & (T_SZ - 1);

    float inv_freq = powf(10000.0f, -(float)(2 * dp) * (1.0f / 128.0f));
    float ang = (float)t * inv_freq;
    float sv, cv;
    sincosf(ang, &sv, &cv);

    __half* p = X + (size_t)bt * (nheads * HD) + h * HD;
    int a0 = kperm(dp), a1 = kperm(dp + 64);
    float x0 = __half2float(p[a0]), x1 = __half2float(p[a1]);
    p[a0] = __float2half(x0 * cv - x1 * sv);
    p[a1] = __float2half(x1 * cv + x0 * sv);
}

// ---------------------------------------------------------------------------
// fp16 tensor-core flash attention (m16n8k16), causal, GQA.
// CTA: 128 queries; KV tiles of 64; 8 warps, warp = 16 q rows x all keys.
// Double-buffered K/Vt, register-resident P.
// Smem (halves): K0 @0 (64x136), K1 @8704, Vt0 @17408 (128x72), Vt1 @26624.
// Q staged transiently @0 (overlaps K0+K1; consumed before first K fill).
// Total 35840 halves = 71680 B.
// ---------------------------------------------------------------------------
#define KPADH 136
#define VPADH 72
#define FA_SMEM (35840 * 2)

__global__ void __launch_bounds__(256, 1)
flash_h(const __half* __restrict__ Q, const __half* __restrict__ K,
        const __half* __restrict__ V, __half* __restrict__ Y) {
    extern __shared__ __half smh[];
    uint32_t smb = (uint32_t)__cvta_generic_to_shared(smh);

    const int bi  = gridDim.x - 1 - blockIdx.x;   // big tiles first
    const int bh  = blockIdx.y;
    const int b   = bh >> 4, h = bh & 15;
    const int kvh = h >> 2;
    const int tid = threadIdx.x;
    const int warp = tid >> 5, lane = tid & 31;
    const int lr = lane >> 2, lc = lane & 3;

    const __half* kg0 = K + (size_t)(b * T_SZ) * 512 + kvh * 128;
    const __half* vg0 = V + (size_t)(b * T_SZ) * 512 + kvh * 128;

    // stage Q tile (fp16, pair-permuted) into smem @0: 128 x 128 halves
    const __half* qg = Q + (size_t)(b * T_SZ + bi * 128) * 2048 + h * 128;
#pragma unroll
    for (int it = 0; it < 8; it++) {
        int idx = it * 256 + tid;
        int r = idx >> 4, c8 = (idx & 15) * 8;
        cp16(smb + (r * KPADH + c8) * 2, qg + (size_t)r * 2048 + c8);
    }
    cp_commit();
    cp_wait<0>();
    __syncthreads();

    uint32_t qa[8][4];
#pragma unroll
    for (int ck = 0; ck < 8; ck++) {
        uint2 v0 = *(const uint2*)(smh + (warp * 16 + lr) * KPADH + ck * 16 + 4 * lc);
        uint2 v1 = *(const uint2*)(smh + (warp * 16 + lr + 8) * KPADH + ck * 16 + 4 * lc);
        qa[ck][0] = v0.x; qa[ck][1] = v1.x;
        qa[ck][2] = v0.y; qa[ck][3] = v1.y;
    }
    __syncthreads();   // all warps done reading Qs before K fills overwrite it

    // V-transpose thread mapping (fixed per thread)
    const int vd = (warp & 3) * 32 + lane;      // d: 0..127
    const int vt0 = (warp >> 2) * 4;            // t start: 0 or 4

    // ---- prologue: fill buffer 0 with kv tile 0 ----
    {
        const __half* kg = kg0;
#pragma unroll
        for (int it = 0; it < 4; it++) {
            int idx = it * 256 + tid;
            int r = idx >> 4, c8 = (idx & 15) * 8;
            cp16(smb + (r * KPADH + c8) * 2, kg + (size_t)r * 512 + c8);
        }
        cp_commit();
        const __half* vg = vg0;
        __half* Vt = smh + 17408;
#pragma unroll
        for (int it = 0; it < 8; it++) {
            int t4 = vt0 + it * 8;
            __half v0 = vg[(size_t)(t4 + 0) * 512 + vd];
            __half v1 = vg[(size_t)(t4 + 1) * 512 + vd];
            __half v2 = vg[(size_t)(t4 + 2) * 512 + vd];
            __half v3 = vg[(size_t)(t4 + 3) * 512 + vd];
            int p = t4 >> 1;
            int chb = (p >> 3) * 16;
            *(half2*)(Vt + vd * VPADH + chb + pslot(p & 7) * 2) = __halves2half2(v0, v1);
            *(half2*)(Vt + vd * VPADH + chb + pslot((p + 1) & 7) * 2) = __halves2half2(v2, v3);
        }
        cp_wait<0>();
        __syncthreads();
    }

    float o[16][4];
#pragma unroll
    for (int nf = 0; nf < 16; nf++)
        o[nf][0] = o[nf][1] = o[nf][2] = o[nf][3] = 0.f;
    float m0 = -1e30f, m1 = -1e30f, l0 = 0.f, l1 = 0.f;

    const float sc = 0.08838834764831845f;   // 1/sqrt(128)
    const int rlo = bi * 128 + warp * 16 + lr;
    const int jmax = 2 * bi + 1;

    for (int j = 0; j <= jmax; j++) {
        const int cur = j & 1;

        // ---- prefetch tile j+1 into the other buffer ----
        if (j < jmax) {
            const int nx = cur ^ 1;
            const __half* kg = kg0 + (size_t)(j + 1) * 64 * 512;
#pragma unroll
            for (int it = 0; it < 4; it++) {
                int idx = it * 256 + tid;
                int r = idx >> 4, c8 = (idx & 15) * 8;
                cp16(smb + (nx * 8704 + r * KPADH + c8) * 2, kg + (size_t)r * 512 + c8);
            }
            cp_commit();
            const __half* vg = vg0 + (size_t)(j + 1) * 64 * 512;
            __half* Vt = smh + 17408 + nx * 9216;
#pragma unroll
            for (int it = 0; it < 8; it++) {
                int t4 = vt0 + it * 8;
                __half v0 = vg[(size_t)(t4 + 0) * 512 + vd];
                __half v1 = vg[(size_t)(t4 + 1) * 512 + vd];
                __half v2 = vg[(size_t)(t4 + 2) * 512 + vd];
                __half v3 = vg[(size_t)(t4 + 3) * 512 + vd];
                int p = t4 >> 1;
                int chb = (p >> 3) * 16;
                *(half2*)(Vt + vd * VPADH + chb + pslot(p & 7) * 2) = __halves2half2(v0, v1);
                *(half2*)(Vt + vd * VPADH + chb + pslot((p + 1) & 7) * 2) = __halves2half2(v2, v3);
            }
        }

        const __half* Ks = smh + cur * 8704;
        const __half* Vc = smh + 17408 + cur * 9216;

        // ---- S = Q K^T (warp: 16 x 64), 8 k16 chunks ----
        float sa[8][4];
#pragma unroll
        for (int nf = 0; nf < 8; nf++)
            sa[nf][0] = sa[nf][1] = sa[nf][2] = sa[nf][3] = 0.f;
#pragma unroll
        for (int ck = 0; ck < 8; ck++) {
            uint32_t bf[8][2];
#pragma unroll
            for (int nf = 0; nf < 8; nf++) {
                uint2 v = *(const uint2*)(Ks + (nf * 8 + lr) * KPADH + ck * 16 + 4 * lc);
                bf[nf][0] = v.x; bf[nf][1] = v.y;
            }
#pragma unroll
            for (int nf = 0; nf < 8; nf++)
                mma_f16(sa[nf], qa[ck], bf[nf]);
        }

        // ---- scale + causal mask ----
        const bool domask = (j >= 2 * bi);
#pragma unroll
        for (int nf = 0; nf < 8; nf++) {
            sa[nf][0] *= sc; sa[nf][1] *= sc;
            sa[nf][2] *= sc; sa[nf][3] *= sc;
            if (domask) {
                int c0 = j * 64 + nf * 8 + 2 * lc;
                if (c0 > rlo)         sa[nf][0] = -1e30f;
                if (c0 + 1 > rlo)     sa[nf][1] = -1e30f;
                if (c0 > rlo + 8)     sa[nf][2] = -1e30f;
                if (c0 + 1 > rlo + 8) sa[nf][3] = -1e30f;
            }
        }

        // ---- online softmax (2 rows/thread, quad reduce); P stays in sa ----
        float mx0 = -1e30f, mx1 = -1e30f;
#pragma unroll
        for (int nf = 0; nf < 8; nf++) {
            mx0 = fmaxf(mx0, fmaxf(sa[nf][0], sa[nf][1]));
            mx1 = fmaxf(mx1, fmaxf(sa[nf][2], sa[nf][3]));
        }
        mx0 = fmaxf(mx0, __shfl_xor_sync(0xffffffffu, mx0, 1));
        mx0 = fmaxf(mx0, __shfl_xor_sync(0xffffffffu, mx0, 2));
        mx1 = fmaxf(mx1, __shfl_xor_sync(0xffffffffu, mx1, 1));
        mx1 = fmaxf(mx1, __shfl_xor_sync(0xffffffffu, mx1, 2));

        float mn0 = fmaxf(m0, mx0), mn1 = fmaxf(m1, mx1);
        float al0 = __expf(m0 - mn0), al1 = __expf(m1 - mn1);
        float s0 = 0.f, s1 = 0.f;
#pragma unroll
        for (int nf = 0; nf < 8; nf++) {
            float p0 = __expf(sa[nf][0] - mn0);
            float p1 = __expf(sa[nf][1] - mn0);
            float p2 = __expf(sa[nf][2] - mn1);
            float p3 = __expf(sa[nf][3] - mn1);
            s0 += p0 + p1; s1 += p2 + p3;
            sa[nf][0] = p0; sa[nf][1] = p1; sa[nf][2] = p2; sa[nf][3] = p3;
        }
        s0 += __shfl_xor_sync(0xffffffffu, s0, 1);
        s0 += __shfl_xor_sync(0xffffffffu, s0, 2);
        s1 += __shfl_xor_sync(0xffffffffu, s1, 1);
        s1 += __shfl_xor_sync(0xffffffffu, s1, 2);
        l0 = l0 * al0 + s0; m0 = mn0;
        l1 = l1 * al1 + s1; m1 = mn1;
#pragma unroll
        for (int nf = 0; nf < 16; nf++) {
            o[nf][0] *= al0; o[nf][1] *= al0;
            o[nf][2] *= al1; o[nf][3] *= al1;
        }

        // ---- O += P V (warp: 16 x 128); P packed directly from registers.
        //      A-frag for k16 chunk ck: a0/a1 from S-tile 2ck (rows lr, lr+8),
        //      a2/a3 from S-tile 2ck+1. Permuted Vt uint2 gives b0=t(2lc,2lc+1),
        //      b1=t(2lc+8,2lc+9) at n-row lr — matching layouts. ----
#pragma unroll
        for (int ck = 0; ck < 4; ck++) {
            uint32_t pa[4];
            pa[0] = f2h2(sa[2 * ck][0],     sa[2 * ck][1]);
            pa[1] = f2h2(sa[2 * ck][2],     sa[2 * ck][3]);
            pa[2] = f2h2(sa[2 * ck + 1][0], sa[2 * ck + 1][1]);
            pa[3] = f2h2(sa[2 * ck + 1][2], sa[2 * ck + 1][3]);
#pragma unroll
            for (int nf = 0; nf < 16; nf++) {
                uint2 bv = *(const uint2*)(Vc + (nf * 8 + lr) * VPADH + ck * 16 + 4 * lc);
                uint32_t bb[2] = {bv.x, bv.y};
                mma_f16(o[nf], pa, bb);
            }
        }

        cp_wait<0>();
        __syncthreads();   // tile j+1 ready; all warps done with buffer cur
    }

    // ---- normalize + store y fp16, pair-permuted (feeds final GEMM) ----
    float inv0 = 1.f / l0, inv1 = 1.f / l1;
    __half* y0 = Y + (size_t)(b * T_SZ + bi * 128 + warp * 16 + lr) * 2048 + h * 128;
    __half* y1 = y0 + 8 * 2048;
#pragma unroll
    for (int nf = 0; nf < 16; nf++) {
        int hc = nf * 8 + 2 * lc;
        int colw = (hc & ~15) + pslot((hc >> 1) & 7) * 2;
        *(half2*)(y0 + colw) = __halves2half2(__float2half(o[nf][0] * inv0),
                                              __float2half(o[nf][1] * inv0));
        *(half2*)(y1 + colw) = __halves2half2(__float2half(o[nf][2] * inv1),
                                              __float2half(o[nf][3] * inv1));
    }
}

// ---------------------------------------------------------------------------
extern "C" void kernel_launch(void* const* d_in, const int* in_sizes, int n_in,
                              void* d_out, int out_size) {
    const float* x  = (const float*)d_in[0];
    const float* wq = (const float*)d_in[1];
    const float* wk = (const float*)d_in[2];
    const float* wv = (const float*)d_in[3];
    const float* wo = (const float*)d_in[4];
    float* out = (float*)d_out;

    __half *qp, *kp, *vp, *yp, *xh, *wqkvT, *woT;
    cudaGetSymbolAddress((void**)&qp,    g_q);
    cudaGetSymbolAddress((void**)&kp,    g_k);
    cudaGetSymbolAddress((void**)&vp,    g_v);
    cudaGetSymbolAddress((void**)&yp,    g_y);
    cudaGetSymbolAddress((void**)&xh,    g_xh);
    cudaGetSymbolAddress((void**)&wqkvT, g_wqkvT);
    cudaGetSymbolAddress((void**)&woT,   g_woT);

    cudaFuncSetAttribute(gemm_h<false>, cudaFuncAttributeMaxDynamicSharedMemorySize, GEMM_SMEM);
    cudaFuncSetAttribute(gemm_h<true>,  cudaFuncAttributeMaxDynamicSharedMemorySize, GEMM_SMEM);
    cudaFuncSetAttribute(flash_h, cudaFuncAttributeMaxDynamicSharedMemorySize, FA_SMEM);

    dim3 tb(32, 8);
    transpose_h<<<dim3(2048 / 32, 2048 / 32), tb>>>(wq, wqkvT,               2048, 2048);
    transpose_h<<<dim3(512  / 32, 2048 / 32), tb>>>(wk, wqkvT + 2048 * 2048, 2048, 512);
    transpose_h<<<dim3(512  / 32, 2048 / 32), tb>>>(wv, wqkvT + 2560 * 2048, 2048, 512);
    transpose_h<<<dim3(2048 / 32, 2048 / 32), tb>>>(wo, woT,                 2048, 2048);

    conv_x<<<(MR * 2048 / 4 + 255) / 256, 256>>>(x, xh, MR * 2048 / 4);

    // Fused QKV projection (N = 3072); q,k head-permuted fp16; v natural fp16
    gemm_h<true><<<dim3(3072 / BN, MR / BM), 256, GEMM_SMEM>>>(
        xh, wqkvT, nullptr, qp, kp, vp, 3072);

    rope_h<<<(MR * NH  * 64 + 255) / 256, 256>>>(qp, NH);
    rope_h<<<(MR * NKV * 64 + 255) / 256, 256>>>(kp, NKV);

    // fp16 tensor-core causal GQA flash attention (double-buffered)
    flash_h<<<dim3(T_SZ / 128, B_SZ * NH), 256, FA_SMEM>>>(qp, kp, vp, yp);

    // Output projection (fp32 out)
    gemm_h<false><<<dim3(2048 / BN, MR / BM), 256, GEMM_SMEM>>>(
        yp, woT, out, nullptr, nullptr, nullptr, 2048);
}